// round 11
// baseline (speedup 1.0000x reference)
#include <cuda_runtime.h>
#include <cuda_bf16.h>
#include <cstdint>

#define N_NODES 100000
#define N_EDGES 1600000
#define DIM 128
#define NLAYER 5

// ---------------- scratch (device globals; no allocations) ----------------
__device__ float g_h[N_NODES * DIM];                 // node features fp32
__device__ __nv_bfloat16 g_aggh[N_NODES * DIM];      // aggregated bf16 hi
__device__ __nv_bfloat16 g_aggl[N_NODES * DIM];      // aggregated bf16 lo
__device__ __nv_bfloat16 g_midh[N_NODES * 2 * DIM];  // MLP hidden bf16 hi
__device__ __nv_bfloat16 g_midl[N_NODES * 2 * DIM];  // MLP hidden bf16 lo
__device__ int   g_rowptr[N_NODES + 1];
__device__ int   g_cursor[N_NODES];
__device__ int   g_cnt[N_NODES];
__device__ int   g_tcnt[N_NODES * 18];               // per-node edge-type histogram
__device__ int   g_edge[N_EDGES];                    // src only
__device__ int   g_bsum[128];
__device__ int   g_boff[128];

#define WSZ (NLAYER * 256 * 128)
__device__ __nv_bfloat16 g_w1h[WSZ];
__device__ __nv_bfloat16 g_w1l[WSZ];
__device__ __nv_bfloat16 g_w2h[WSZ];
__device__ __nv_bfloat16 g_w2l[WSZ];

// ---------------- setup ----------------
__global__ void k_wt(const float* __restrict__ w1, const float* __restrict__ w2) {
    int i = blockIdx.x * blockDim.x + threadIdx.x;
    if (i >= WSZ) return;
    float a = w1[i];
    __nv_bfloat16 h = __float2bfloat16_rn(a);
    g_w1h[i] = h;
    g_w1l[i] = __float2bfloat16_rn(a - __bfloat162float(h));
    float b = w2[i];
    __nv_bfloat16 h2 = __float2bfloat16_rn(b);
    g_w2h[i] = h2;
    g_w2l[i] = __float2bfloat16_rn(b - __bfloat162float(h2));
}

__global__ void k_zero(int n) {
    int i = blockIdx.x * blockDim.x + threadIdx.x;
    if (i < n) g_cnt[i] = 0;
    if (i < n * 18) g_tcnt[i] = 0;
}

__global__ void k_count(const int* __restrict__ dst, const int* __restrict__ eattr, int E) {
    int e = blockIdx.x * blockDim.x + threadIdx.x;
    if (e >= E) return;
    int d = dst[e];
    atomicAdd(&g_cnt[d], 1);
    int ci = eattr[2 * e] * 3 + eattr[2 * e + 1];
    atomicAdd(&g_tcnt[d * 18 + ci], 1);
}

__global__ void k_bsum(int n) {
    __shared__ int wsum[32];
    int i = blockIdx.x * 1024 + threadIdx.x;
    int lane = threadIdx.x & 31, wid = threadIdx.x >> 5;
    int v = (i < n) ? g_cnt[i] : 0;
    int s = v;
    #pragma unroll
    for (int o = 16; o > 0; o >>= 1) s += __shfl_down_sync(0xffffffffu, s, o);
    if (lane == 0) wsum[wid] = s;
    __syncthreads();
    if (wid == 0) {
        int t = wsum[lane];
        #pragma unroll
        for (int o = 16; o > 0; o >>= 1) t += __shfl_down_sync(0xffffffffu, t, o);
        if (lane == 0) g_bsum[blockIdx.x] = t;
    }
}
__global__ void k_boff(int nblk) {
    __shared__ int ws[4];
    int lane = threadIdx.x & 31, wid = threadIdx.x >> 5;
    int v = (threadIdx.x < nblk) ? g_bsum[threadIdx.x] : 0;
    int s = v;
    #pragma unroll
    for (int o = 1; o < 32; o <<= 1) {
        int t = __shfl_up_sync(0xffffffffu, s, o);
        if (lane >= o) s += t;
    }
    if (lane == 31) ws[wid] = s;
    __syncthreads();
    if (wid == 0 && lane < 4) {
        int t = ws[lane];
        #pragma unroll
        for (int o = 1; o < 4; o <<= 1) {
            int u = __shfl_up_sync(0xfu, t, o);
            if (lane >= o) t += u;
        }
        ws[lane] = t;
    }
    __syncthreads();
    int excl = s - v + (wid ? ws[wid - 1] : 0);
    if (threadIdx.x < nblk) g_boff[threadIdx.x] = excl;
}
__global__ void k_local(int n) {
    __shared__ int wsum[32];
    int i = blockIdx.x * 1024 + threadIdx.x;
    int lane = threadIdx.x & 31, wid = threadIdx.x >> 5;
    int v = (i < n) ? g_cnt[i] : 0;
    int s = v;
    #pragma unroll
    for (int o = 1; o < 32; o <<= 1) {
        int t = __shfl_up_sync(0xffffffffu, s, o);
        if (lane >= o) s += t;
    }
    if (lane == 31) wsum[wid] = s;
    __syncthreads();
    if (wid == 0) {
        int t = wsum[lane];
        #pragma unroll
        for (int o = 1; o < 32; o <<= 1) {
            int u = __shfl_up_sync(0xffffffffu, t, o);
            if (lane >= o) t += u;
        }
        wsum[lane] = t;
    }
    __syncthreads();
    int excl = s - v + (wid ? wsum[wid - 1] : 0) + g_boff[blockIdx.x];
    if (i < n) {
        g_rowptr[i] = excl;
        g_cursor[i] = excl;
        if (i == n - 1) g_rowptr[n] = excl + v;
    }
}
__global__ void k_fill(const int* __restrict__ src, const int* __restrict__ dst, int E) {
    int e = blockIdx.x * blockDim.x + threadIdx.x;
    if (e >= E) return;
    int d = dst[e];
    int pos = atomicAdd(&g_cursor[d], 1);
    g_edge[pos] = src[e];
}

// ---------------- node input embedding ----------------
__global__ void k_embed(const int* __restrict__ x, const float* __restrict__ xemb, int n) {
    int i = blockIdx.x * blockDim.x + threadIdx.x;
    int v = i >> 5, c = (i & 31) * 4;
    if (v >= n) return;
    int a = x[2 * v], ch = x[2 * v + 1];
    float4 va = *(const float4*)(xemb + (size_t)a * DIM + c);
    float4 vb = *(const float4*)(xemb + (size_t)(120 + ch) * DIM + c);
    float4 r;
    r.x = va.x + vb.x; r.y = va.y + vb.y; r.z = va.z + vb.z; r.w = va.w + vb.w;
    *(float4*)(g_h + (size_t)v * DIM + c) = r;
}

// ---------------- aggregation: one warp per node, unroll 8 ----------------
__global__ void k_agg(const float* __restrict__ etab_l, int n) {
    __shared__ float4 ctb[18 * 32];
    for (int i = threadIdx.x; i < 18 * 32; i += blockDim.x) {
        int comb = i >> 5, ln = i & 31;
        int eb = comb / 3, ed = comb - eb * 3;
        float4 b = ((const float4*)etab_l)[eb * 32 + ln];
        float4 d = ((const float4*)(etab_l + 6 * DIM))[ed * 32 + ln];
        ctb[i] = make_float4(b.x + d.x, b.y + d.y, b.z + d.z, b.w + d.w);
    }
    __syncthreads();
    int w = (blockIdx.x * blockDim.x + threadIdx.x) >> 5;
    int lane = threadIdx.x & 31;
    if (w >= n) return;
    int beg = g_rowptr[w], end = g_rowptr[w + 1];
    float4 acc0 = *(const float4*)(g_h + (size_t)w * DIM + lane * 4);
    float4 acc1 = make_float4(0.f, 0.f, 0.f, 0.f);
    float4 acc2 = make_float4(0.f, 0.f, 0.f, 0.f);
    float4 acc3 = make_float4(0.f, 0.f, 0.f, 0.f);
    // edge-type contribution via per-node histogram (self-loop = type 12)
    const int* tc = g_tcnt + (size_t)w * 18;
    #pragma unroll
    for (int t = 0; t < 18; t++) {
        float c = (float)(tc[t] + (t == 12 ? 1 : 0));
        float4 e = ctb[t * 32 + lane];
        acc0.x += c * e.x; acc0.y += c * e.y;
        acc0.z += c * e.z; acc0.w += c * e.w;
    }
    int p = beg;
    for (; p + 8 <= end; p += 8) {
        int s0 = g_edge[p],     s1 = g_edge[p + 1], s2 = g_edge[p + 2], s3 = g_edge[p + 3];
        int s4 = g_edge[p + 4], s5 = g_edge[p + 5], s6 = g_edge[p + 6], s7 = g_edge[p + 7];
        float4 h0 = *(const float4*)(g_h + (size_t)s0 * DIM + lane * 4);
        float4 h1 = *(const float4*)(g_h + (size_t)s1 * DIM + lane * 4);
        float4 h2 = *(const float4*)(g_h + (size_t)s2 * DIM + lane * 4);
        float4 h3 = *(const float4*)(g_h + (size_t)s3 * DIM + lane * 4);
        float4 h4 = *(const float4*)(g_h + (size_t)s4 * DIM + lane * 4);
        float4 h5 = *(const float4*)(g_h + (size_t)s5 * DIM + lane * 4);
        float4 h6 = *(const float4*)(g_h + (size_t)s6 * DIM + lane * 4);
        float4 h7 = *(const float4*)(g_h + (size_t)s7 * DIM + lane * 4);
        acc0.x += h0.x; acc0.y += h0.y; acc0.z += h0.z; acc0.w += h0.w;
        acc1.x += h1.x; acc1.y += h1.y; acc1.z += h1.z; acc1.w += h1.w;
        acc2.x += h2.x; acc2.y += h2.y; acc2.z += h2.z; acc2.w += h2.w;
        acc3.x += h3.x; acc3.y += h3.y; acc3.z += h3.z; acc3.w += h3.w;
        acc0.x += h4.x; acc0.y += h4.y; acc0.z += h4.z; acc0.w += h4.w;
        acc1.x += h5.x; acc1.y += h5.y; acc1.z += h5.z; acc1.w += h5.w;
        acc2.x += h6.x; acc2.y += h6.y; acc2.z += h6.z; acc2.w += h6.w;
        acc3.x += h7.x; acc3.y += h7.y; acc3.z += h7.z; acc3.w += h7.w;
    }
    for (; p + 4 <= end; p += 4) {
        int s0 = g_edge[p], s1 = g_edge[p + 1], s2 = g_edge[p + 2], s3 = g_edge[p + 3];
        float4 h0 = *(const float4*)(g_h + (size_t)s0 * DIM + lane * 4);
        float4 h1 = *(const float4*)(g_h + (size_t)s1 * DIM + lane * 4);
        float4 h2 = *(const float4*)(g_h + (size_t)s2 * DIM + lane * 4);
        float4 h3 = *(const float4*)(g_h + (size_t)s3 * DIM + lane * 4);
        acc0.x += h0.x; acc0.y += h0.y; acc0.z += h0.z; acc0.w += h0.w;
        acc1.x += h1.x; acc1.y += h1.y; acc1.z += h1.z; acc1.w += h1.w;
        acc2.x += h2.x; acc2.y += h2.y; acc2.z += h2.z; acc2.w += h2.w;
        acc3.x += h3.x; acc3.y += h3.y; acc3.z += h3.z; acc3.w += h3.w;
    }
    for (; p < end; p++) {
        int s = g_edge[p];
        float4 hv = *(const float4*)(g_h + (size_t)s * DIM + lane * 4);
        acc0.x += hv.x; acc0.y += hv.y; acc0.z += hv.z; acc0.w += hv.w;
    }
    acc0.x += acc1.x + acc2.x + acc3.x;
    acc0.y += acc1.y + acc2.y + acc3.y;
    acc0.z += acc1.z + acc2.z + acc3.z;
    acc0.w += acc1.w + acc2.w + acc3.w;
    __nv_bfloat16 h0 = __float2bfloat16_rn(acc0.x);
    __nv_bfloat16 h1 = __float2bfloat16_rn(acc0.y);
    __nv_bfloat16 h2 = __float2bfloat16_rn(acc0.z);
    __nv_bfloat16 h3 = __float2bfloat16_rn(acc0.w);
    __nv_bfloat162 hp0 = {h0, h1}, hp1 = {h2, h3};
    __nv_bfloat162 lp0 = {__float2bfloat16_rn(acc0.x - __bfloat162float(h0)),
                          __float2bfloat16_rn(acc0.y - __bfloat162float(h1))};
    __nv_bfloat162 lp1 = {__float2bfloat16_rn(acc0.z - __bfloat162float(h2)),
                          __float2bfloat16_rn(acc0.w - __bfloat162float(h3))};
    size_t o = (size_t)w * DIM + lane * 4;
    *(uint2*)(g_aggh + o) = make_uint2(*(uint32_t*)&hp0, *(uint32_t*)&hp1);
    *(uint2*)(g_aggl + o) = make_uint2(*(uint32_t*)&lp0, *(uint32_t*)&lp1);
}

// ---------------- mma.sync GEMM: C[M,JTOT] = A[M,KTOT] @ W[JTOT,KTOT]^T ----------------
// A pre-split bf16 hi/lo. D = Ahi*Whi + Ahi*Wlo + Alo*Whi (fp32 accum).
// OSPLIT: write output as bf16 hi/lo (Oh/Ol); else fp32 to C.
#define SROWB 144
#define TILE_B (128 * SROWB)
#define OFF_SCALE 0
#define OFF_SHIFT 512
#define OFF_AHI 1024
#define OFF_ALO (OFF_AHI + TILE_B)
#define OFF_BHI (OFF_ALO + TILE_B)
#define OFF_BLO (OFF_BHI + TILE_B)
#define MMA_SMEM (OFF_BLO + TILE_B)        // 74752 bytes

__device__ __forceinline__ uint32_t smem_u32(const void* p) {
    uint32_t a;
    asm("{ .reg .u64 t; cvta.to.shared.u64 t, %1; cvt.u32.u64 %0, t; }" : "=r"(a) : "l"(p));
    return a;
}
__device__ __forceinline__ void ldsm4(uint32_t* r, uint32_t addr) {
    asm volatile("ldmatrix.sync.aligned.m8n8.x4.shared.b16 {%0,%1,%2,%3}, [%4];"
                 : "=r"(r[0]), "=r"(r[1]), "=r"(r[2]), "=r"(r[3]) : "r"(addr));
}
__device__ __forceinline__ void mma16816(float* d, const uint32_t* a,
                                         uint32_t b0, uint32_t b1) {
    asm volatile(
        "mma.sync.aligned.m16n8k16.row.col.f32.bf16.bf16.f32 "
        "{%0,%1,%2,%3}, {%4,%5,%6,%7}, {%8,%9}, {%0,%1,%2,%3};"
        : "+f"(d[0]), "+f"(d[1]), "+f"(d[2]), "+f"(d[3])
        : "r"(a[0]), "r"(a[1]), "r"(a[2]), "r"(a[3]), "r"(b0), "r"(b1));
}

template <int KTOT, int JTOT, bool BN, bool RELU, bool OSPLIT>
__global__ void __launch_bounds__(256)
k_mma(const __nv_bfloat16* __restrict__ Ah, const __nv_bfloat16* __restrict__ Al,
      const __nv_bfloat16* __restrict__ Wh, const __nv_bfloat16* __restrict__ Wl,
      const float* __restrict__ bias,
      const float* __restrict__ gamma, const float* __restrict__ beta,
      const float* __restrict__ mean, const float* __restrict__ var,
      float* __restrict__ C, __nv_bfloat16* __restrict__ Oh,
      __nv_bfloat16* __restrict__ Ol, int M) {
    extern __shared__ char sm[];
    uint32_t sb = smem_u32(sm);
    float* s_scale = (float*)(sm + OFF_SCALE);
    float* s_shift = (float*)(sm + OFF_SHIFT);
    int tid = threadIdx.x;
    int wid = tid >> 5, lane = tid & 31;
    int mb = blockIdx.x, jbase = blockIdx.y * 128;
    int wm = wid >> 1, wn = wid & 1;

    if (tid < 128) {
        int j = jbase + tid;
        if (BN) {
            float s = gamma[j] * rsqrtf(var[j] + 1e-5f);
            s_scale[tid] = s;
            s_shift[tid] = (bias[j] - mean[j]) * s + beta[j];
        } else {
            s_scale[tid] = 1.f;
            s_shift[tid] = bias[j];
        }
    }

    float acc[2][8][4];
    #pragma unroll
    for (int a = 0; a < 2; a++)
        #pragma unroll
        for (int b = 0; b < 8; b++)
            #pragma unroll
            for (int c = 0; c < 4; c++) acc[a][b][c] = 0.f;

    int lr = lane & 15, lc8 = lane >> 4;
    const uint4 zero4 = make_uint4(0u, 0u, 0u, 0u);

    for (int kb = 0; kb < KTOT; kb += 64) {
        // stage A: pure 16B copies of pre-split hi/lo
        #pragma unroll
        for (int t = 0; t < 4; t++) {
            int idx = tid + t * 256;
            int row = idx >> 3;
            int k8 = (idx & 7) * 8;
            int rg = mb * 128 + row;
            uint32_t off = row * SROWB + k8 * 2;
            if (rg < M) {
                size_t gsrc = (size_t)rg * KTOT + kb + k8;
                *(uint4*)(sm + OFF_AHI + off) = *(const uint4*)(Ah + gsrc);
                *(uint4*)(sm + OFF_ALO + off) = *(const uint4*)(Al + gsrc);
            } else {
                *(uint4*)(sm + OFF_AHI + off) = zero4;
                *(uint4*)(sm + OFF_ALO + off) = zero4;
            }
        }
        // stage B (pre-split bf16 weights)
        #pragma unroll
        for (int t = 0; t < 4; t++) {
            int idx = tid + t * 256;
            int j = idx >> 3;
            int k8 = (idx & 7) * 8;
            size_t gsrc = (size_t)(jbase + j) * KTOT + kb + k8;
            uint32_t off = j * SROWB + k8 * 2;
            *(uint4*)(sm + OFF_BHI + off) = *(const uint4*)(Wh + gsrc);
            *(uint4*)(sm + OFF_BLO + off) = *(const uint4*)(Wl + gsrc);
        }
        __syncthreads();

        #pragma unroll
        for (int ks = 0; ks < 4; ks++) {
            uint32_t ah[2][4], al[2][4];
            #pragma unroll
            for (int mf = 0; mf < 2; mf++) {
                uint32_t aoff = (uint32_t)((wm * 32 + mf * 16 + lr) * SROWB +
                                           ks * 32 + lc8 * 16);
                ldsm4(ah[mf], sb + OFF_AHI + aoff);
                ldsm4(al[mf], sb + OFF_ALO + aoff);
            }
            #pragma unroll
            for (int p = 0; p < 4; p++) {
                uint32_t bh[4], bl[4];
                uint32_t boff = (uint32_t)((wn * 64 + p * 16 + lr) * SROWB +
                                           ks * 32 + lc8 * 16);
                ldsm4(bh, sb + OFF_BHI + boff);
                ldsm4(bl, sb + OFF_BLO + boff);
                #pragma unroll
                for (int mf = 0; mf < 2; mf++) {
                    mma16816(acc[mf][2 * p],     ah[mf], bh[0], bh[2]);
                    mma16816(acc[mf][2 * p],     ah[mf], bl[0], bl[2]);
                    mma16816(acc[mf][2 * p],     al[mf], bh[0], bh[2]);
                    mma16816(acc[mf][2 * p + 1], ah[mf], bh[1], bh[3]);
                    mma16816(acc[mf][2 * p + 1], ah[mf], bl[1], bl[3]);
                    mma16816(acc[mf][2 * p + 1], al[mf], bh[1], bh[3]);
                }
            }
        }
        __syncthreads();
    }

    // epilogue
    #pragma unroll
    for (int mf = 0; mf < 2; mf++) {
        int row0 = mb * 128 + wm * 32 + mf * 16 + (lane >> 2);
        int row1 = row0 + 8;
        #pragma unroll
        for (int nf = 0; nf < 8; nf++) {
            int col = wn * 64 + nf * 8 + (lane & 3) * 2;
            float s0 = s_scale[col], s1 = s_scale[col + 1];
            float t0 = s_shift[col], t1 = s_shift[col + 1];
            float v0 = acc[mf][nf][0] * s0 + t0;
            float v1 = acc[mf][nf][1] * s1 + t1;
            float v2 = acc[mf][nf][2] * s0 + t0;
            float v3 = acc[mf][nf][3] * s1 + t1;
            if (RELU) {
                v0 = fmaxf(v0, 0.f); v1 = fmaxf(v1, 0.f);
                v2 = fmaxf(v2, 0.f); v3 = fmaxf(v3, 0.f);
            }
            if (OSPLIT) {
                if (row0 < M) {
                    __nv_bfloat16 a = __float2bfloat16_rn(v0), b = __float2bfloat16_rn(v1);
                    __nv_bfloat162 hp = {a, b};
                    __nv_bfloat162 lp = {__float2bfloat16_rn(v0 - __bfloat162float(a)),
                                         __float2bfloat16_rn(v1 - __bfloat162float(b))};
                    size_t o = (size_t)row0 * JTOT + jbase + col;
                    *(uint32_t*)(Oh + o) = *(uint32_t*)&hp;
                    *(uint32_t*)(Ol + o) = *(uint32_t*)&lp;
                }
                if (row1 < M) {
                    __nv_bfloat16 a = __float2bfloat16_rn(v2), b = __float2bfloat16_rn(v3);
                    __nv_bfloat162 hp = {a, b};
                    __nv_bfloat162 lp = {__float2bfloat16_rn(v2 - __bfloat162float(a)),
                                         __float2bfloat16_rn(v3 - __bfloat162float(b))};
                    size_t o = (size_t)row1 * JTOT + jbase + col;
                    *(uint32_t*)(Oh + o) = *(uint32_t*)&hp;
                    *(uint32_t*)(Ol + o) = *(uint32_t*)&lp;
                }
            } else {
                if (row0 < M)
                    *(float2*)(C + (size_t)row0 * JTOT + jbase + col) = make_float2(v0, v1);
                if (row1 < M)
                    *(float2*)(C + (size_t)row1 * JTOT + jbase + col) = make_float2(v2, v3);
            }
        }
    }
}

// ---------------- launch ----------------
extern "C" void kernel_launch(void* const* d_in, const int* in_sizes, int n_in,
                              void* d_out, int out_size) {
    const int*   x     = (const int*)d_in[0];
    const int*   eidx  = (const int*)d_in[1];
    const int*   eattr = (const int*)d_in[2];
    const float* xemb  = (const float*)d_in[3];
    const float* etab  = (const float*)d_in[4];
    const float* w1    = (const float*)d_in[5];
    const float* b1    = (const float*)d_in[6];
    const float* w2    = (const float*)d_in[7];
    const float* b2    = (const float*)d_in[8];
    const float* gamma = (const float*)d_in[9];
    const float* beta  = (const float*)d_in[10];
    const float* bnm   = (const float*)d_in[11];
    const float* bnv   = (const float*)d_in[12];
    float* out = (float*)d_out;

    int n = in_sizes[0] / 2;
    int E = in_sizes[1] / 2;
    const int* srcp = eidx;
    const int* dstp = eidx + E;

    cudaFuncSetAttribute(k_mma<128, 256, false, true, true>,
                         cudaFuncAttributeMaxDynamicSharedMemorySize, MMA_SMEM);
    cudaFuncSetAttribute(k_mma<256, 128, true, true, false>,
                         cudaFuncAttributeMaxDynamicSharedMemorySize, MMA_SMEM);
    cudaFuncSetAttribute(k_mma<256, 128, true, false, false>,
                         cudaFuncAttributeMaxDynamicSharedMemorySize, MMA_SMEM);

    void *ph, *pah, *pal, *pmh, *pml, *p1h, *p1l, *p2h, *p2l;
    cudaGetSymbolAddress(&ph, g_h);
    cudaGetSymbolAddress(&pah, g_aggh);
    cudaGetSymbolAddress(&pal, g_aggl);
    cudaGetSymbolAddress(&pmh, g_midh);
    cudaGetSymbolAddress(&pml, g_midl);
    cudaGetSymbolAddress(&p1h, g_w1h);
    cudaGetSymbolAddress(&p1l, g_w1l);
    cudaGetSymbolAddress(&p2h, g_w2h);
    cudaGetSymbolAddress(&p2l, g_w2l);
    float* H = (float*)ph;
    __nv_bfloat16* AGH = (__nv_bfloat16*)pah;
    __nv_bfloat16* AGL = (__nv_bfloat16*)pal;
    __nv_bfloat16* MIDH = (__nv_bfloat16*)pmh;
    __nv_bfloat16* MIDL = (__nv_bfloat16*)pml;
    const __nv_bfloat16* W1H = (const __nv_bfloat16*)p1h;
    const __nv_bfloat16* W1L = (const __nv_bfloat16*)p1l;
    const __nv_bfloat16* W2H = (const __nv_bfloat16*)p2h;
    const __nv_bfloat16* W2L = (const __nv_bfloat16*)p2l;

    int nblk = (n + 1023) / 1024;

    k_wt<<<(WSZ + 255) / 256, 256>>>(w1, w2);
    k_zero<<<(n * 18 + 255) / 256, 256>>>(n);
    k_count<<<(E + 255) / 256, 256>>>(dstp, eattr, E);
    k_bsum<<<nblk, 1024>>>(n);
    k_boff<<<1, 128>>>(nblk);
    k_local<<<nblk, 1024>>>(n);
    k_fill<<<(E + 255) / 256, 256>>>(srcp, dstp, E);
    k_embed<<<(n * 32 + 255) / 256, 256>>>(x, xemb, n);

    int mblocks = (n + 127) / 128;
    for (int l = 0; l < NLAYER; l++) {
        k_agg<<<(n * 32 + 255) / 256, 256>>>(etab + (size_t)l * 9 * DIM, n);
        // GEMM1: agg(bf16 hi/lo) @ W1^T -> MID bf16 hi/lo, bias+ReLU
        k_mma<128, 256, false, true, true><<<dim3(mblocks, 2), 256, MMA_SMEM>>>(
            AGH, AGL,
            W1H + (size_t)l * 256 * 128, W1L + (size_t)l * 256 * 128,
            b1 + (size_t)l * 2 * DIM,
            nullptr, nullptr, nullptr, nullptr, nullptr, MIDH, MIDL, n);
        // GEMM2: MID(bf16 hi/lo) @ W2^T -> H/out fp32, bias+BN(+ReLU)
        const float* g = gamma + (size_t)l * DIM;
        const float* bt = beta + (size_t)l * DIM;
        const float* mn = bnm + (size_t)l * DIM;
        const float* vr = bnv + (size_t)l * DIM;
        const __nv_bfloat16* W2Hl = W2H + (size_t)l * 128 * 256;
        const __nv_bfloat16* W2Ll = W2L + (size_t)l * 128 * 256;
        const float* B2 = b2 + (size_t)l * DIM;
        if (l < NLAYER - 1) {
            k_mma<256, 128, true, true, false><<<dim3(mblocks, 1), 256, MMA_SMEM>>>(
                MIDH, MIDL, W2Hl, W2Ll, B2, g, bt, mn, vr, H, nullptr, nullptr, n);
        } else {
            k_mma<256, 128, true, false, false><<<dim3(mblocks, 1), 256, MMA_SMEM>>>(
                MIDH, MIDL, W2Hl, W2Ll, B2, g, bt, mn, vr, out, nullptr, nullptr, n);
        }
    }
}

// round 12
// speedup vs baseline: 1.0592x; 1.0592x over previous
#include <cuda_runtime.h>
#include <cuda_bf16.h>
#include <cstdint>

#define N_NODES 100000
#define N_EDGES 1600000
#define DIM 128
#define NLAYER 5

// ---------------- scratch (device globals; no allocations) ----------------
__device__ float g_h[N_NODES * DIM];                 // node features fp32
__device__ __nv_bfloat16 g_aggh[N_NODES * DIM];      // aggregated bf16 hi
__device__ __nv_bfloat16 g_aggl[N_NODES * DIM];      // aggregated bf16 lo
__device__ __nv_bfloat16 g_midh[N_NODES * 2 * DIM];  // MLP hidden bf16 hi
__device__ __nv_bfloat16 g_midl[N_NODES * 2 * DIM];  // MLP hidden bf16 lo
__device__ int   g_rowptr[N_NODES + 1];
__device__ int   g_cursor[N_NODES];
__device__ int   g_cnt[N_NODES];
__device__ int   g_tcnt[N_NODES * 18];               // per-node edge-type histogram
__device__ int   g_edge[N_EDGES];                    // src only
__device__ int   g_bsum[128];
__device__ int   g_boff[128];

#define WSZ (NLAYER * 256 * 128)
__device__ __nv_bfloat16 g_w1h[WSZ];
__device__ __nv_bfloat16 g_w1l[WSZ];
__device__ __nv_bfloat16 g_w2h[WSZ];
__device__ __nv_bfloat16 g_w2l[WSZ];

// ---------------- setup ----------------
__global__ void k_wt(const float* __restrict__ w1, const float* __restrict__ w2) {
    int i = blockIdx.x * blockDim.x + threadIdx.x;
    if (i >= WSZ) return;
    float a = w1[i];
    __nv_bfloat16 h = __float2bfloat16_rn(a);
    g_w1h[i] = h;
    g_w1l[i] = __float2bfloat16_rn(a - __bfloat162float(h));
    float b = w2[i];
    __nv_bfloat16 h2 = __float2bfloat16_rn(b);
    g_w2h[i] = h2;
    g_w2l[i] = __float2bfloat16_rn(b - __bfloat162float(h2));
}

__global__ void k_zero(int n) {
    int i = blockIdx.x * blockDim.x + threadIdx.x;
    if (i < n) g_cnt[i] = 0;
    if (i < n * 18) g_tcnt[i] = 0;
}

__global__ void k_count(const int* __restrict__ dst, const int* __restrict__ eattr, int E) {
    int e = blockIdx.x * blockDim.x + threadIdx.x;
    if (e >= E) return;
    int d = dst[e];
    atomicAdd(&g_cnt[d], 1);
    int ci = eattr[2 * e] * 3 + eattr[2 * e + 1];
    atomicAdd(&g_tcnt[d * 18 + ci], 1);
}

__global__ void k_bsum(int n) {
    __shared__ int wsum[32];
    int i = blockIdx.x * 1024 + threadIdx.x;
    int lane = threadIdx.x & 31, wid = threadIdx.x >> 5;
    int v = (i < n) ? g_cnt[i] : 0;
    int s = v;
    #pragma unroll
    for (int o = 16; o > 0; o >>= 1) s += __shfl_down_sync(0xffffffffu, s, o);
    if (lane == 0) wsum[wid] = s;
    __syncthreads();
    if (wid == 0) {
        int t = wsum[lane];
        #pragma unroll
        for (int o = 16; o > 0; o >>= 1) t += __shfl_down_sync(0xffffffffu, t, o);
        if (lane == 0) g_bsum[blockIdx.x] = t;
    }
}
__global__ void k_boff(int nblk) {
    __shared__ int ws[4];
    int lane = threadIdx.x & 31, wid = threadIdx.x >> 5;
    int v = (threadIdx.x < nblk) ? g_bsum[threadIdx.x] : 0;
    int s = v;
    #pragma unroll
    for (int o = 1; o < 32; o <<= 1) {
        int t = __shfl_up_sync(0xffffffffu, s, o);
        if (lane >= o) s += t;
    }
    if (lane == 31) ws[wid] = s;
    __syncthreads();
    if (wid == 0 && lane < 4) {
        int t = ws[lane];
        #pragma unroll
        for (int o = 1; o < 4; o <<= 1) {
            int u = __shfl_up_sync(0xfu, t, o);
            if (lane >= o) t += u;
        }
        ws[lane] = t;
    }
    __syncthreads();
    int excl = s - v + (wid ? ws[wid - 1] : 0);
    if (threadIdx.x < nblk) g_boff[threadIdx.x] = excl;
}
__global__ void k_local(int n) {
    __shared__ int wsum[32];
    int i = blockIdx.x * 1024 + threadIdx.x;
    int lane = threadIdx.x & 31, wid = threadIdx.x >> 5;
    int v = (i < n) ? g_cnt[i] : 0;
    int s = v;
    #pragma unroll
    for (int o = 1; o < 32; o <<= 1) {
        int t = __shfl_up_sync(0xffffffffu, s, o);
        if (lane >= o) s += t;
    }
    if (lane == 31) wsum[wid] = s;
    __syncthreads();
    if (wid == 0) {
        int t = wsum[lane];
        #pragma unroll
        for (int o = 1; o < 32; o <<= 1) {
            int u = __shfl_up_sync(0xffffffffu, t, o);
            if (lane >= o) t += u;
        }
        wsum[lane] = t;
    }
    __syncthreads();
    int excl = s - v + (wid ? wsum[wid - 1] : 0) + g_boff[blockIdx.x];
    if (i < n) {
        g_rowptr[i] = excl;
        g_cursor[i] = excl;
        if (i == n - 1) g_rowptr[n] = excl + v;
    }
}
__global__ void k_fill(const int* __restrict__ src, const int* __restrict__ dst, int E) {
    int e = blockIdx.x * blockDim.x + threadIdx.x;
    if (e >= E) return;
    int d = dst[e];
    int pos = atomicAdd(&g_cursor[d], 1);
    g_edge[pos] = src[e];
}

// ---------------- node input embedding ----------------
__global__ void k_embed(const int* __restrict__ x, const float* __restrict__ xemb, int n) {
    int i = blockIdx.x * blockDim.x + threadIdx.x;
    int v = i >> 5, c = (i & 31) * 4;
    if (v >= n) return;
    int a = x[2 * v], ch = x[2 * v + 1];
    float4 va = *(const float4*)(xemb + (size_t)a * DIM + c);
    float4 vb = *(const float4*)(xemb + (size_t)(120 + ch) * DIM + c);
    float4 r;
    r.x = va.x + vb.x; r.y = va.y + vb.y; r.z = va.z + vb.z; r.w = va.w + vb.w;
    *(float4*)(g_h + (size_t)v * DIM + c) = r;
}

// ---------------- aggregation: one warp per node (R9 proven body, unroll 4) ----------------
__global__ void k_agg(const float* __restrict__ etab_l, int n) {
    __shared__ float4 ctb[18 * 32];
    for (int i = threadIdx.x; i < 18 * 32; i += blockDim.x) {
        int comb = i >> 5, ln = i & 31;
        int eb = comb / 3, ed = comb - eb * 3;
        float4 b = ((const float4*)etab_l)[eb * 32 + ln];
        float4 d = ((const float4*)(etab_l + 6 * DIM))[ed * 32 + ln];
        ctb[i] = make_float4(b.x + d.x, b.y + d.y, b.z + d.z, b.w + d.w);
    }
    __syncthreads();
    int w = (blockIdx.x * blockDim.x + threadIdx.x) >> 5;
    int lane = threadIdx.x & 31;
    if (w >= n) return;
    int beg = g_rowptr[w], end = g_rowptr[w + 1];
    float4 acc0 = *(const float4*)(g_h + (size_t)w * DIM + lane * 4);
    float4 acc1 = make_float4(0.f, 0.f, 0.f, 0.f);
    float4 acc2 = make_float4(0.f, 0.f, 0.f, 0.f);
    float4 acc3 = make_float4(0.f, 0.f, 0.f, 0.f);
    const int* tc = g_tcnt + (size_t)w * 18;
    #pragma unroll
    for (int t = 0; t < 18; t++) {
        float c = (float)(tc[t] + (t == 12 ? 1 : 0));
        float4 e = ctb[t * 32 + lane];
        acc0.x += c * e.x; acc0.y += c * e.y;
        acc0.z += c * e.z; acc0.w += c * e.w;
    }
    int p = beg;
    for (; p + 4 <= end; p += 4) {
        int s0 = g_edge[p], s1 = g_edge[p + 1], s2 = g_edge[p + 2], s3 = g_edge[p + 3];
        float4 h0 = *(const float4*)(g_h + (size_t)s0 * DIM + lane * 4);
        float4 h1 = *(const float4*)(g_h + (size_t)s1 * DIM + lane * 4);
        float4 h2 = *(const float4*)(g_h + (size_t)s2 * DIM + lane * 4);
        float4 h3 = *(const float4*)(g_h + (size_t)s3 * DIM + lane * 4);
        acc0.x += h0.x; acc0.y += h0.y; acc0.z += h0.z; acc0.w += h0.w;
        acc1.x += h1.x; acc1.y += h1.y; acc1.z += h1.z; acc1.w += h1.w;
        acc2.x += h2.x; acc2.y += h2.y; acc2.z += h2.z; acc2.w += h2.w;
        acc3.x += h3.x; acc3.y += h3.y; acc3.z += h3.z; acc3.w += h3.w;
    }
    for (; p < end; p++) {
        int s = g_edge[p];
        float4 hv = *(const float4*)(g_h + (size_t)s * DIM + lane * 4);
        acc0.x += hv.x; acc0.y += hv.y; acc0.z += hv.z; acc0.w += hv.w;
    }
    acc0.x += acc1.x + acc2.x + acc3.x;
    acc0.y += acc1.y + acc2.y + acc3.y;
    acc0.z += acc1.z + acc2.z + acc3.z;
    acc0.w += acc1.w + acc2.w + acc3.w;
    __nv_bfloat16 h0 = __float2bfloat16_rn(acc0.x);
    __nv_bfloat16 h1 = __float2bfloat16_rn(acc0.y);
    __nv_bfloat16 h2 = __float2bfloat16_rn(acc0.z);
    __nv_bfloat16 h3 = __float2bfloat16_rn(acc0.w);
    __nv_bfloat162 hp0 = {h0, h1}, hp1 = {h2, h3};
    __nv_bfloat162 lp0 = {__float2bfloat16_rn(acc0.x - __bfloat162float(h0)),
                          __float2bfloat16_rn(acc0.y - __bfloat162float(h1))};
    __nv_bfloat162 lp1 = {__float2bfloat16_rn(acc0.z - __bfloat162float(h2)),
                          __float2bfloat16_rn(acc0.w - __bfloat162float(h3))};
    size_t o = (size_t)w * DIM + lane * 4;
    *(uint2*)(g_aggh + o) = make_uint2(*(uint32_t*)&hp0, *(uint32_t*)&hp1);
    *(uint2*)(g_aggl + o) = make_uint2(*(uint32_t*)&lp0, *(uint32_t*)&lp1);
}

// ---------------- pipelined mma.sync GEMM ----------------
// C[M,JTOT] = A[M,KTOT] @ W[JTOT,KTOT]^T, A pre-split bf16 hi/lo.
// D = Ahi*Whi + Ahi*Wlo + Alo*Whi (fp32 accum). CTA 128x128, 8 warps.
// 2-stage cp.async double buffer over 64-wide K chunks.
#define SROWB 144
#define TILE_B (128 * SROWB)               // 18432
#define STAGE_B (4 * TILE_B)               // 73728: AHI | ALO | BHI | BLO
#define MMA_SMEM (1024 + 2 * STAGE_B)      // 148480

__device__ __forceinline__ uint32_t smem_u32(const void* p) {
    uint32_t a;
    asm("{ .reg .u64 t; cvta.to.shared.u64 t, %1; cvt.u32.u64 %0, t; }" : "=r"(a) : "l"(p));
    return a;
}
__device__ __forceinline__ void cpa16(uint32_t dst, const void* src, int sz) {
    asm volatile("cp.async.cg.shared.global [%0], [%1], 16, %2;"
                 :: "r"(dst), "l"(src), "r"(sz) : "memory");
}
#define CP_COMMIT() asm volatile("cp.async.commit_group;" ::: "memory")
template <int N> __device__ __forceinline__ void cp_wait() {
    asm volatile("cp.async.wait_group %0;" :: "n"(N) : "memory");
}
__device__ __forceinline__ void ldsm4(uint32_t* r, uint32_t addr) {
    asm volatile("ldmatrix.sync.aligned.m8n8.x4.shared.b16 {%0,%1,%2,%3}, [%4];"
                 : "=r"(r[0]), "=r"(r[1]), "=r"(r[2]), "=r"(r[3]) : "r"(addr));
}
__device__ __forceinline__ void mma16816(float* d, const uint32_t* a,
                                         uint32_t b0, uint32_t b1) {
    asm volatile(
        "mma.sync.aligned.m16n8k16.row.col.f32.bf16.bf16.f32 "
        "{%0,%1,%2,%3}, {%4,%5,%6,%7}, {%8,%9}, {%0,%1,%2,%3};"
        : "+f"(d[0]), "+f"(d[1]), "+f"(d[2]), "+f"(d[3])
        : "r"(a[0]), "r"(a[1]), "r"(a[2]), "r"(a[3]), "r"(b0), "r"(b1));
}

template <int KTOT, int JTOT, bool BN, bool RELU, bool OSPLIT>
__global__ void __launch_bounds__(256)
k_mma(const __nv_bfloat16* __restrict__ Ah, const __nv_bfloat16* __restrict__ Al,
      const __nv_bfloat16* __restrict__ Wh, const __nv_bfloat16* __restrict__ Wl,
      const float* __restrict__ bias,
      const float* __restrict__ gamma, const float* __restrict__ beta,
      const float* __restrict__ mean, const float* __restrict__ var,
      float* __restrict__ C, __nv_bfloat16* __restrict__ Oh,
      __nv_bfloat16* __restrict__ Ol, int M) {
    extern __shared__ char sm[];
    uint32_t sb = smem_u32(sm);
    float* s_scale = (float*)(sm);
    float* s_shift = (float*)(sm + 512);
    int tid = threadIdx.x;
    int wid = tid >> 5, lane = tid & 31;
    int mb = blockIdx.x, jbase = blockIdx.y * 128;
    int wm = wid >> 1, wn = wid & 1;

    if (tid < 128) {
        int j = jbase + tid;
        if (BN) {
            float s = gamma[j] * rsqrtf(var[j] + 1e-5f);
            s_scale[tid] = s;
            s_shift[tid] = (bias[j] - mean[j]) * s + beta[j];
        } else {
            s_scale[tid] = 1.f;
            s_shift[tid] = bias[j];
        }
    }

    float acc[2][8][4];
    #pragma unroll
    for (int a = 0; a < 2; a++)
        #pragma unroll
        for (int b = 0; b < 8; b++)
            #pragma unroll
            for (int c = 0; c < 4; c++) acc[a][b][c] = 0.f;

    int lr = lane & 15, lc8 = lane >> 4;
    constexpr int NKB = KTOT / 64;

    // staging: pure 16B cp.async copies of pre-split tiles into stage s
    auto stage_load = [&](int s, int kb) {
        uint32_t stb = sb + 1024 + s * STAGE_B;
        #pragma unroll
        for (int t = 0; t < 4; t++) {
            int idx = tid + t * 256;
            int row = idx >> 3;
            int k8 = (idx & 7) * 8;
            int rg = mb * 128 + row;
            int sz = (rg < M) ? 16 : 0;
            uint32_t off = stb + row * SROWB + k8 * 2;
            size_t gsrc = (size_t)rg * KTOT + kb + k8;
            cpa16(off, Ah + gsrc, sz);
            cpa16(off + TILE_B, Al + gsrc, sz);
        }
        #pragma unroll
        for (int t = 0; t < 4; t++) {
            int idx = tid + t * 256;
            int j = idx >> 3;
            int k8 = (idx & 7) * 8;
            size_t gsrc = (size_t)(jbase + j) * KTOT + kb + k8;
            uint32_t off = stb + 2 * TILE_B + j * SROWB + k8 * 2;
            cpa16(off, Wh + gsrc, 16);
            cpa16(off + TILE_B, Wl + gsrc, 16);
        }
    };

    stage_load(0, 0);
    CP_COMMIT();

    #pragma unroll
    for (int i = 0; i < NKB; i++) {
        if (i + 1 < NKB) {
            stage_load((i + 1) & 1, (i + 1) * 64);
            CP_COMMIT();
            cp_wait<1>();
        } else {
            cp_wait<0>();
        }
        __syncthreads();

        uint32_t stb = sb + 1024 + (i & 1) * STAGE_B;
        #pragma unroll
        for (int ks = 0; ks < 4; ks++) {
            uint32_t ah[2][4], al[2][4];
            #pragma unroll
            for (int mf = 0; mf < 2; mf++) {
                uint32_t aoff = stb + (uint32_t)((wm * 32 + mf * 16 + lr) * SROWB +
                                                 ks * 32 + lc8 * 16);
                ldsm4(ah[mf], aoff);
                ldsm4(al[mf], aoff + TILE_B);
            }
            #pragma unroll
            for (int p = 0; p < 4; p++) {
                uint32_t bh[4], bl[4];
                uint32_t boff = stb + 2 * TILE_B +
                                (uint32_t)((wn * 64 + p * 16 + lr) * SROWB +
                                           ks * 32 + lc8 * 16);
                ldsm4(bh, boff);
                ldsm4(bl, boff + TILE_B);
                #pragma unroll
                for (int mf = 0; mf < 2; mf++) {
                    mma16816(acc[mf][2 * p],     ah[mf], bh[0], bh[2]);
                    mma16816(acc[mf][2 * p],     ah[mf], bl[0], bl[2]);
                    mma16816(acc[mf][2 * p],     al[mf], bh[0], bh[2]);
                    mma16816(acc[mf][2 * p + 1], ah[mf], bh[1], bh[3]);
                    mma16816(acc[mf][2 * p + 1], ah[mf], bl[1], bl[3]);
                    mma16816(acc[mf][2 * p + 1], al[mf], bh[1], bh[3]);
                }
            }
        }
        __syncthreads();
    }

    // epilogue
    #pragma unroll
    for (int mf = 0; mf < 2; mf++) {
        int row0 = mb * 128 + wm * 32 + mf * 16 + (lane >> 2);
        int row1 = row0 + 8;
        #pragma unroll
        for (int nf = 0; nf < 8; nf++) {
            int col = wn * 64 + nf * 8 + (lane & 3) * 2;
            float s0 = s_scale[col], s1 = s_scale[col + 1];
            float t0 = s_shift[col], t1 = s_shift[col + 1];
            float v0 = acc[mf][nf][0] * s0 + t0;
            float v1 = acc[mf][nf][1] * s1 + t1;
            float v2 = acc[mf][nf][2] * s0 + t0;
            float v3 = acc[mf][nf][3] * s1 + t1;
            if (RELU) {
                v0 = fmaxf(v0, 0.f); v1 = fmaxf(v1, 0.f);
                v2 = fmaxf(v2, 0.f); v3 = fmaxf(v3, 0.f);
            }
            if (OSPLIT) {
                if (row0 < M) {
                    __nv_bfloat16 a = __float2bfloat16_rn(v0), b = __float2bfloat16_rn(v1);
                    __nv_bfloat162 hp = {a, b};
                    __nv_bfloat162 lp = {__float2bfloat16_rn(v0 - __bfloat162float(a)),
                                         __float2bfloat16_rn(v1 - __bfloat162float(b))};
                    size_t o = (size_t)row0 * JTOT + jbase + col;
                    *(uint32_t*)(Oh + o) = *(uint32_t*)&hp;
                    *(uint32_t*)(Ol + o) = *(uint32_t*)&lp;
                }
                if (row1 < M) {
                    __nv_bfloat16 a = __float2bfloat16_rn(v2), b = __float2bfloat16_rn(v3);
                    __nv_bfloat162 hp = {a, b};
                    __nv_bfloat162 lp = {__float2bfloat16_rn(v2 - __bfloat162float(a)),
                                         __float2bfloat16_rn(v3 - __bfloat162float(b))};
                    size_t o = (size_t)row1 * JTOT + jbase + col;
                    *(uint32_t*)(Oh + o) = *(uint32_t*)&hp;
                    *(uint32_t*)(Ol + o) = *(uint32_t*)&lp;
                }
            } else {
                if (row0 < M)
                    *(float2*)(C + (size_t)row0 * JTOT + jbase + col) = make_float2(v0, v1);
                if (row1 < M)
                    *(float2*)(C + (size_t)row1 * JTOT + jbase + col) = make_float2(v2, v3);
            }
        }
    }
}

// ---------------- launch ----------------
extern "C" void kernel_launch(void* const* d_in, const int* in_sizes, int n_in,
                              void* d_out, int out_size) {
    const int*   x     = (const int*)d_in[0];
    const int*   eidx  = (const int*)d_in[1];
    const int*   eattr = (const int*)d_in[2];
    const float* xemb  = (const float*)d_in[3];
    const float* etab  = (const float*)d_in[4];
    const float* w1    = (const float*)d_in[5];
    const float* b1    = (const float*)d_in[6];
    const float* w2    = (const float*)d_in[7];
    const float* b2    = (const float*)d_in[8];
    const float* gamma = (const float*)d_in[9];
    const float* beta  = (const float*)d_in[10];
    const float* bnm   = (const float*)d_in[11];
    const float* bnv   = (const float*)d_in[12];
    float* out = (float*)d_out;

    int n = in_sizes[0] / 2;
    int E = in_sizes[1] / 2;
    const int* srcp = eidx;
    const int* dstp = eidx + E;

    cudaFuncSetAttribute(k_mma<128, 256, false, true, true>,
                         cudaFuncAttributeMaxDynamicSharedMemorySize, MMA_SMEM);
    cudaFuncSetAttribute(k_mma<256, 128, true, true, false>,
                         cudaFuncAttributeMaxDynamicSharedMemorySize, MMA_SMEM);
    cudaFuncSetAttribute(k_mma<256, 128, true, false, false>,
                         cudaFuncAttributeMaxDynamicSharedMemorySize, MMA_SMEM);

    void *ph, *pah, *pal, *pmh, *pml, *p1h, *p1l, *p2h, *p2l;
    cudaGetSymbolAddress(&ph, g_h);
    cudaGetSymbolAddress(&pah, g_aggh);
    cudaGetSymbolAddress(&pal, g_aggl);
    cudaGetSymbolAddress(&pmh, g_midh);
    cudaGetSymbolAddress(&pml, g_midl);
    cudaGetSymbolAddress(&p1h, g_w1h);
    cudaGetSymbolAddress(&p1l, g_w1l);
    cudaGetSymbolAddress(&p2h, g_w2h);
    cudaGetSymbolAddress(&p2l, g_w2l);
    float* H = (float*)ph;
    __nv_bfloat16* AGH = (__nv_bfloat16*)pah;
    __nv_bfloat16* AGL = (__nv_bfloat16*)pal;
    __nv_bfloat16* MIDH = (__nv_bfloat16*)pmh;
    __nv_bfloat16* MIDL = (__nv_bfloat16*)pml;
    const __nv_bfloat16* W1H = (const __nv_bfloat16*)p1h;
    const __nv_bfloat16* W1L = (const __nv_bfloat16*)p1l;
    const __nv_bfloat16* W2H = (const __nv_bfloat16*)p2h;
    const __nv_bfloat16* W2L = (const __nv_bfloat16*)p2l;

    int nblk = (n + 1023) / 1024;

    k_wt<<<(WSZ + 255) / 256, 256>>>(w1, w2);
    k_zero<<<(n * 18 + 255) / 256, 256>>>(n);
    k_count<<<(E + 255) / 256, 256>>>(dstp, eattr, E);
    k_bsum<<<nblk, 1024>>>(n);
    k_boff<<<1, 128>>>(nblk);
    k_local<<<nblk, 1024>>>(n);
    k_fill<<<(E + 255) / 256, 256>>>(srcp, dstp, E);
    k_embed<<<(n * 32 + 255) / 256, 256>>>(x, xemb, n);

    int mblocks = (n + 127) / 128;
    for (int l = 0; l < NLAYER; l++) {
        k_agg<<<(n * 32 + 255) / 256, 256>>>(etab + (size_t)l * 9 * DIM, n);
        // GEMM1: agg(bf16 hi/lo) @ W1^T -> MID bf16 hi/lo, bias+ReLU
        k_mma<128, 256, false, true, true><<<dim3(mblocks, 2), 256, MMA_SMEM>>>(
            AGH, AGL,
            W1H + (size_t)l * 256 * 128, W1L + (size_t)l * 256 * 128,
            b1 + (size_t)l * 2 * DIM,
            nullptr, nullptr, nullptr, nullptr, nullptr, MIDH, MIDL, n);
        // GEMM2: MID(bf16 hi/lo) @ W2^T -> H/out fp32, bias+BN(+ReLU)
        const float* g = gamma + (size_t)l * DIM;
        const float* bt = beta + (size_t)l * DIM;
        const float* mn = bnm + (size_t)l * DIM;
        const float* vr = bnv + (size_t)l * DIM;
        const __nv_bfloat16* W2Hl = W2H + (size_t)l * 128 * 256;
        const __nv_bfloat16* W2Ll = W2L + (size_t)l * 128 * 256;
        const float* B2 = b2 + (size_t)l * DIM;
        if (l < NLAYER - 1) {
            k_mma<256, 128, true, true, false><<<dim3(mblocks, 1), 256, MMA_SMEM>>>(
                MIDH, MIDL, W2Hl, W2Ll, B2, g, bt, mn, vr, H, nullptr, nullptr, n);
        } else {
            k_mma<256, 128, true, false, false><<<dim3(mblocks, 1), 256, MMA_SMEM>>>(
                MIDH, MIDL, W2Hl, W2Ll, B2, g, bt, mn, vr, out, nullptr, nullptr, n);
        }
    }
}

// round 14
// speedup vs baseline: 1.1719x; 1.1064x over previous
#include <cuda_runtime.h>
#include <cuda_bf16.h>
#include <cstdint>

#define N_NODES 100000
#define N_EDGES 1600000
#define DIM 128
#define NLAYER 5

// ---------------- scratch (device globals; no allocations) ----------------
__device__ float g_h[N_NODES * DIM];                 // node features fp32
__device__ __nv_bfloat16 g_aggh[N_NODES * DIM];      // aggregated bf16 hi
__device__ __nv_bfloat16 g_aggl[N_NODES * DIM];      // aggregated bf16 lo
__device__ __nv_bfloat16 g_midh[N_NODES * 2 * DIM];  // MLP hidden bf16 hi
__device__ __nv_bfloat16 g_midl[N_NODES * 2 * DIM];  // MLP hidden bf16 lo
__device__ int   g_rowptr[N_NODES + 1];
__device__ int   g_cursor[N_NODES];
__device__ int   g_cnt[N_NODES];
__device__ int   g_tcnt[N_NODES * 18];               // per-node edge-type histogram
__device__ int   g_edge[N_EDGES];                    // src only
__device__ int   g_bsum[128];
__device__ int   g_boff[128];

#define WSZ (NLAYER * 256 * 128)
__device__ __nv_bfloat16 g_w1h[WSZ];
__device__ __nv_bfloat16 g_w1l[WSZ];
__device__ __nv_bfloat16 g_w2h[WSZ];
__device__ __nv_bfloat16 g_w2l[WSZ];

// ---------------- setup ----------------
__global__ void k_wt(const float* __restrict__ w1, const float* __restrict__ w2) {
    int i = blockIdx.x * blockDim.x + threadIdx.x;
    if (i >= WSZ) return;
    float a = w1[i];
    __nv_bfloat16 h = __float2bfloat16_rn(a);
    g_w1h[i] = h;
    g_w1l[i] = __float2bfloat16_rn(a - __bfloat162float(h));
    float b = w2[i];
    __nv_bfloat16 h2 = __float2bfloat16_rn(b);
    g_w2h[i] = h2;
    g_w2l[i] = __float2bfloat16_rn(b - __bfloat162float(h2));
}

__global__ void k_zero(int n) {
    int i = blockIdx.x * blockDim.x + threadIdx.x;
    if (i < n) g_cnt[i] = 0;
    if (i < n * 18) g_tcnt[i] = 0;
}

__global__ void k_count(const int* __restrict__ dst, const int* __restrict__ eattr, int E) {
    int e = blockIdx.x * blockDim.x + threadIdx.x;
    if (e >= E) return;
    int d = dst[e];
    atomicAdd(&g_cnt[d], 1);
    int ci = eattr[2 * e] * 3 + eattr[2 * e + 1];
    atomicAdd(&g_tcnt[d * 18 + ci], 1);
}

__global__ void k_bsum(int n) {
    __shared__ int wsum[32];
    int i = blockIdx.x * 1024 + threadIdx.x;
    int lane = threadIdx.x & 31, wid = threadIdx.x >> 5;
    int v = (i < n) ? g_cnt[i] : 0;
    int s = v;
    #pragma unroll
    for (int o = 16; o > 0; o >>= 1) s += __shfl_down_sync(0xffffffffu, s, o);
    if (lane == 0) wsum[wid] = s;
    __syncthreads();
    if (wid == 0) {
        int t = wsum[lane];
        #pragma unroll
        for (int o = 16; o > 0; o >>= 1) t += __shfl_down_sync(0xffffffffu, t, o);
        if (lane == 0) g_bsum[blockIdx.x] = t;
    }
}
__global__ void k_boff(int nblk) {
    __shared__ int ws[4];
    int lane = threadIdx.x & 31, wid = threadIdx.x >> 5;
    int v = (threadIdx.x < nblk) ? g_bsum[threadIdx.x] : 0;
    int s = v;
    #pragma unroll
    for (int o = 1; o < 32; o <<= 1) {
        int t = __shfl_up_sync(0xffffffffu, s, o);
        if (lane >= o) s += t;
    }
    if (lane == 31) ws[wid] = s;
    __syncthreads();
    if (wid == 0 && lane < 4) {
        int t = ws[lane];
        #pragma unroll
        for (int o = 1; o < 4; o <<= 1) {
            int u = __shfl_up_sync(0xfu, t, o);
            if (lane >= o) t += u;
        }
        ws[lane] = t;
    }
    __syncthreads();
    int excl = s - v + (wid ? ws[wid - 1] : 0);
    if (threadIdx.x < nblk) g_boff[threadIdx.x] = excl;
}
__global__ void k_local(int n) {
    __shared__ int wsum[32];
    int i = blockIdx.x * 1024 + threadIdx.x;
    int lane = threadIdx.x & 31, wid = threadIdx.x >> 5;
    int v = (i < n) ? g_cnt[i] : 0;
    int s = v;
    #pragma unroll
    for (int o = 1; o < 32; o <<= 1) {
        int t = __shfl_up_sync(0xffffffffu, s, o);
        if (lane >= o) s += t;
    }
    if (lane == 31) wsum[wid] = s;
    __syncthreads();
    if (wid == 0) {
        int t = wsum[lane];
        #pragma unroll
        for (int o = 1; o < 32; o <<= 1) {
            int u = __shfl_up_sync(0xffffffffu, t, o);
            if (lane >= o) t += u;
        }
        wsum[lane] = t;
    }
    __syncthreads();
    int excl = s - v + (wid ? wsum[wid - 1] : 0) + g_boff[blockIdx.x];
    if (i < n) {
        g_rowptr[i] = excl;
        g_cursor[i] = excl;
        if (i == n - 1) g_rowptr[n] = excl + v;
    }
}
__global__ void k_fill(const int* __restrict__ src, const int* __restrict__ dst, int E) {
    int e = blockIdx.x * blockDim.x + threadIdx.x;
    if (e >= E) return;
    int d = dst[e];
    int pos = atomicAdd(&g_cursor[d], 1);
    g_edge[pos] = src[e];
}

// ---------------- node input embedding ----------------
__global__ void k_embed(const int* __restrict__ x, const float* __restrict__ xemb, int n) {
    int i = blockIdx.x * blockDim.x + threadIdx.x;
    int v = i >> 5, c = (i & 31) * 4;
    if (v >= n) return;
    int a = x[2 * v], ch = x[2 * v + 1];
    float4 va = *(const float4*)(xemb + (size_t)a * DIM + c);
    float4 vb = *(const float4*)(xemb + (size_t)(120 + ch) * DIM + c);
    float4 r;
    r.x = va.x + vb.x; r.y = va.y + vb.y; r.z = va.z + vb.z; r.w = va.w + vb.w;
    *(float4*)(g_h + (size_t)v * DIM + c) = r;
}

// ---------------- aggregation: one warp per node (R9 proven body, unroll 4) ----------------
__global__ void k_agg(const float* __restrict__ etab_l, int n) {
    __shared__ float4 ctb[18 * 32];
    for (int i = threadIdx.x; i < 18 * 32; i += blockDim.x) {
        int comb = i >> 5, ln = i & 31;
        int eb = comb / 3, ed = comb - eb * 3;
        float4 b = ((const float4*)etab_l)[eb * 32 + ln];
        float4 d = ((const float4*)(etab_l + 6 * DIM))[ed * 32 + ln];
        ctb[i] = make_float4(b.x + d.x, b.y + d.y, b.z + d.z, b.w + d.w);
    }
    __syncthreads();
    int w = (blockIdx.x * blockDim.x + threadIdx.x) >> 5;
    int lane = threadIdx.x & 31;
    if (w >= n) return;
    int beg = g_rowptr[w], end = g_rowptr[w + 1];
    float4 acc0 = *(const float4*)(g_h + (size_t)w * DIM + lane * 4);
    float4 acc1 = make_float4(0.f, 0.f, 0.f, 0.f);
    float4 acc2 = make_float4(0.f, 0.f, 0.f, 0.f);
    float4 acc3 = make_float4(0.f, 0.f, 0.f, 0.f);
    const int* tc = g_tcnt + (size_t)w * 18;
    #pragma unroll
    for (int t = 0; t < 18; t++) {
        float c = (float)(tc[t] + (t == 12 ? 1 : 0));
        float4 e = ctb[t * 32 + lane];
        acc0.x += c * e.x; acc0.y += c * e.y;
        acc0.z += c * e.z; acc0.w += c * e.w;
    }
    int p = beg;
    for (; p + 4 <= end; p += 4) {
        int s0 = g_edge[p], s1 = g_edge[p + 1], s2 = g_edge[p + 2], s3 = g_edge[p + 3];
        float4 h0 = *(const float4*)(g_h + (size_t)s0 * DIM + lane * 4);
        float4 h1 = *(const float4*)(g_h + (size_t)s1 * DIM + lane * 4);
        float4 h2 = *(const float4*)(g_h + (size_t)s2 * DIM + lane * 4);
        float4 h3 = *(const float4*)(g_h + (size_t)s3 * DIM + lane * 4);
        acc0.x += h0.x; acc0.y += h0.y; acc0.z += h0.z; acc0.w += h0.w;
        acc1.x += h1.x; acc1.y += h1.y; acc1.z += h1.z; acc1.w += h1.w;
        acc2.x += h2.x; acc2.y += h2.y; acc2.z += h2.z; acc2.w += h2.w;
        acc3.x += h3.x; acc3.y += h3.y; acc3.z += h3.z; acc3.w += h3.w;
    }
    for (; p < end; p++) {
        int s = g_edge[p];
        float4 hv = *(const float4*)(g_h + (size_t)s * DIM + lane * 4);
        acc0.x += hv.x; acc0.y += hv.y; acc0.z += hv.z; acc0.w += hv.w;
    }
    acc0.x += acc1.x + acc2.x + acc3.x;
    acc0.y += acc1.y + acc2.y + acc3.y;
    acc0.z += acc1.z + acc2.z + acc3.z;
    acc0.w += acc1.w + acc2.w + acc3.w;
    __nv_bfloat16 h0 = __float2bfloat16_rn(acc0.x);
    __nv_bfloat16 h1 = __float2bfloat16_rn(acc0.y);
    __nv_bfloat16 h2 = __float2bfloat16_rn(acc0.z);
    __nv_bfloat16 h3 = __float2bfloat16_rn(acc0.w);
    __nv_bfloat162 hp0 = {h0, h1}, hp1 = {h2, h3};
    __nv_bfloat162 lp0 = {__float2bfloat16_rn(acc0.x - __bfloat162float(h0)),
                          __float2bfloat16_rn(acc0.y - __bfloat162float(h1))};
    __nv_bfloat162 lp1 = {__float2bfloat16_rn(acc0.z - __bfloat162float(h2)),
                          __float2bfloat16_rn(acc0.w - __bfloat162float(h3))};
    size_t o = (size_t)w * DIM + lane * 4;
    *(uint2*)(g_aggh + o) = make_uint2(*(uint32_t*)&hp0, *(uint32_t*)&hp1);
    *(uint2*)(g_aggl + o) = make_uint2(*(uint32_t*)&lp0, *(uint32_t*)&lp1);
}

// ---------------- pipelined mma.sync GEMM, 2 CTAs/SM ----------------
// C[M,JTOT] = A[M,KTOT] @ W[JTOT,KTOT]^T, A pre-split bf16 hi/lo.
// D = Ahi*Whi + Ahi*Wlo + Alo*Whi (fp32 accum). CTA 128x128, 8 warps.
// 2-stage cp.async double buffer over 32-wide K chunks -> 82.9KB smem -> 2 CTA/SM.
#define SROWB 80                            // 64B data + 16B pad per 32-k row
#define TILE_B (128 * SROWB)                // 10240
#define STAGE_B (4 * TILE_B)                // 40960: AHI | ALO | BHI | BLO
#define MMA_SMEM (1024 + 2 * STAGE_B)       // 82944

__device__ __forceinline__ uint32_t smem_u32(const void* p) {
    uint32_t a;
    asm("{ .reg .u64 t; cvta.to.shared.u64 t, %1; cvt.u32.u64 %0, t; }" : "=r"(a) : "l"(p));
    return a;
}
__device__ __forceinline__ void cpa16(uint32_t dst, const void* src, int sz) {
    asm volatile("cp.async.cg.shared.global [%0], [%1], 16, %2;"
                 :: "r"(dst), "l"(src), "r"(sz) : "memory");
}
#define CP_COMMIT() asm volatile("cp.async.commit_group;" ::: "memory")
template <int N> __device__ __forceinline__ void cp_wait() {
    asm volatile("cp.async.wait_group %0;" :: "n"(N) : "memory");
}
__device__ __forceinline__ void ldsm4(uint32_t* r, uint32_t addr) {
    asm volatile("ldmatrix.sync.aligned.m8n8.x4.shared.b16 {%0,%1,%2,%3}, [%4];"
                 : "=r"(r[0]), "=r"(r[1]), "=r"(r[2]), "=r"(r[3]) : "r"(addr));
}
__device__ __forceinline__ void mma16816(float* d, const uint32_t* a,
                                         uint32_t b0, uint32_t b1) {
    asm volatile(
        "mma.sync.aligned.m16n8k16.row.col.f32.bf16.bf16.f32 "
        "{%0,%1,%2,%3}, {%4,%5,%6,%7}, {%8,%9}, {%0,%1,%2,%3};"
        : "+f"(d[0]), "+f"(d[1]), "+f"(d[2]), "+f"(d[3])
        : "r"(a[0]), "r"(a[1]), "r"(a[2]), "r"(a[3]), "r"(b0), "r"(b1));
}

template <int KTOT, int JTOT, bool BN, bool RELU, bool OSPLIT>
__global__ void __launch_bounds__(256, 2)
k_mma(const __nv_bfloat16* __restrict__ Ah, const __nv_bfloat16* __restrict__ Al,
      const __nv_bfloat16* __restrict__ Wh, const __nv_bfloat16* __restrict__ Wl,
      const float* __restrict__ bias,
      const float* __restrict__ gamma, const float* __restrict__ beta,
      const float* __restrict__ mean, const float* __restrict__ var,
      float* __restrict__ C, __nv_bfloat16* __restrict__ Oh,
      __nv_bfloat16* __restrict__ Ol, int M) {
    extern __shared__ char sm[];
    uint32_t sb = smem_u32(sm);
    float* s_scale = (float*)(sm);
    float* s_shift = (float*)(sm + 512);
    int tid = threadIdx.x;
    int wid = tid >> 5, lane = tid & 31;
    int mb = blockIdx.x, jbase = blockIdx.y * 128;
    int wm = wid >> 1, wn = wid & 1;

    if (tid < 128) {
        int j = jbase + tid;
        if (BN) {
            float s = gamma[j] * rsqrtf(var[j] + 1e-5f);
            s_scale[tid] = s;
            s_shift[tid] = (bias[j] - mean[j]) * s + beta[j];
        } else {
            s_scale[tid] = 1.f;
            s_shift[tid] = bias[j];
        }
    }

    float acc[2][8][4];
    #pragma unroll
    for (int a = 0; a < 2; a++)
        #pragma unroll
        for (int b = 0; b < 8; b++)
            #pragma unroll
            for (int c = 0; c < 4; c++) acc[a][b][c] = 0.f;

    int lr = lane & 15, lc8 = lane >> 4;
    constexpr int NKB = KTOT / 32;

    // staging: pure 16B cp.async copies of pre-split tiles into stage s (32-wide K chunk)
    auto stage_load = [&](int s, int kb) {
        uint32_t stb = sb + 1024 + s * STAGE_B;
        #pragma unroll
        for (int t = 0; t < 2; t++) {
            int idx = tid + t * 256;          // 0..511
            int row = idx >> 2;               // 0..127
            int k8 = (idx & 3) * 8;           // 0,8,16,24
            int rg = mb * 128 + row;
            int sz = (rg < M) ? 16 : 0;
            uint32_t off = stb + row * SROWB + k8 * 2;
            size_t gsrc = (size_t)rg * KTOT + kb + k8;
            cpa16(off, Ah + gsrc, sz);
            cpa16(off + TILE_B, Al + gsrc, sz);
        }
        #pragma unroll
        for (int t = 0; t < 2; t++) {
            int idx = tid + t * 256;
            int j = idx >> 2;
            int k8 = (idx & 3) * 8;
            size_t gsrc = (size_t)(jbase + j) * KTOT + kb + k8;
            uint32_t off = stb + 2 * TILE_B + j * SROWB + k8 * 2;
            cpa16(off, Wh + gsrc, 16);
            cpa16(off + TILE_B, Wl + gsrc, 16);
        }
    };

    stage_load(0, 0);
    CP_COMMIT();

    #pragma unroll
    for (int i = 0; i < NKB; i++) {
        if (i + 1 < NKB) {
            stage_load((i + 1) & 1, (i + 1) * 32);
            CP_COMMIT();
            cp_wait<1>();
        } else {
            cp_wait<0>();
        }
        __syncthreads();

        uint32_t stb = sb + 1024 + (i & 1) * STAGE_B;
        #pragma unroll
        for (int ks = 0; ks < 2; ks++) {
            uint32_t ah[2][4], al[2][4];
            #pragma unroll
            for (int mf = 0; mf < 2; mf++) {
                uint32_t aoff = stb + (uint32_t)((wm * 32 + mf * 16 + lr) * SROWB +
                                                 ks * 32 + lc8 * 16);
                ldsm4(ah[mf], aoff);
                ldsm4(al[mf], aoff + TILE_B);
            }
            #pragma unroll
            for (int p = 0; p < 4; p++) {
                uint32_t bh[4], bl[4];
                uint32_t boff = stb + 2 * TILE_B +
                                (uint32_t)((wn * 64 + p * 16 + lr) * SROWB +
                                           ks * 32 + lc8 * 16);
                ldsm4(bh, boff);
                ldsm4(bl, boff + TILE_B);
                #pragma unroll
                for (int mf = 0; mf < 2; mf++) {
                    mma16816(acc[mf][2 * p],     ah[mf], bh[0], bh[2]);
                    mma16816(acc[mf][2 * p],     ah[mf], bl[0], bl[2]);
                    mma16816(acc[mf][2 * p],     al[mf], bh[0], bh[2]);
                    mma16816(acc[mf][2 * p + 1], ah[mf], bh[1], bh[3]);
                    mma16816(acc[mf][2 * p + 1], ah[mf], bl[1], bl[3]);
                    mma16816(acc[mf][2 * p + 1], al[mf], bh[1], bh[3]);
                }
            }
        }
        __syncthreads();
    }

    // epilogue
    #pragma unroll
    for (int mf = 0; mf < 2; mf++) {
        int row0 = mb * 128 + wm * 32 + mf * 16 + (lane >> 2);
        int row1 = row0 + 8;
        #pragma unroll
        for (int nf = 0; nf < 8; nf++) {
            int col = wn * 64 + nf * 8 + (lane & 3) * 2;
            float s0 = s_scale[col], s1 = s_scale[col + 1];
            float t0 = s_shift[col], t1 = s_shift[col + 1];
            float v0 = acc[mf][nf][0] * s0 + t0;
            float v1 = acc[mf][nf][1] * s1 + t1;
            float v2 = acc[mf][nf][2] * s0 + t0;
            float v3 = acc[mf][nf][3] * s1 + t1;
            if (RELU) {
                v0 = fmaxf(v0, 0.f); v1 = fmaxf(v1, 0.f);
                v2 = fmaxf(v2, 0.f); v3 = fmaxf(v3, 0.f);
            }
            if (OSPLIT) {
                if (row0 < M) {
                    __nv_bfloat16 a = __float2bfloat16_rn(v0), b = __float2bfloat16_rn(v1);
                    __nv_bfloat162 hp = {a, b};
                    __nv_bfloat162 lp = {__float2bfloat16_rn(v0 - __bfloat162float(a)),
                                         __float2bfloat16_rn(v1 - __bfloat162float(b))};
                    size_t o = (size_t)row0 * JTOT + jbase + col;
                    *(uint32_t*)(Oh + o) = *(uint32_t*)&hp;
                    *(uint32_t*)(Ol + o) = *(uint32_t*)&lp;
                }
                if (row1 < M) {
                    __nv_bfloat16 a = __float2bfloat16_rn(v2), b = __float2bfloat16_rn(v3);
                    __nv_bfloat162 hp = {a, b};
                    __nv_bfloat162 lp = {__float2bfloat16_rn(v2 - __bfloat162float(a)),
                                         __float2bfloat16_rn(v3 - __bfloat162float(b))};
                    size_t o = (size_t)row1 * JTOT + jbase + col;
                    *(uint32_t*)(Oh + o) = *(uint32_t*)&hp;
                    *(uint32_t*)(Ol + o) = *(uint32_t*)&lp;
                }
            } else {
                if (row0 < M)
                    *(float2*)(C + (size_t)row0 * JTOT + jbase + col) = make_float2(v0, v1);
                if (row1 < M)
                    *(float2*)(C + (size_t)row1 * JTOT + jbase + col) = make_float2(v2, v3);
            }
        }
    }
}

// ---------------- launch ----------------
extern "C" void kernel_launch(void* const* d_in, const int* in_sizes, int n_in,
                              void* d_out, int out_size) {
    const int*   x     = (const int*)d_in[0];
    const int*   eidx  = (const int*)d_in[1];
    const int*   eattr = (const int*)d_in[2];
    const float* xemb  = (const float*)d_in[3];
    const float* etab  = (const float*)d_in[4];
    const float* w1    = (const float*)d_in[5];
    const float* b1    = (const float*)d_in[6];
    const float* w2    = (const float*)d_in[7];
    const float* b2    = (const float*)d_in[8];
    const float* gamma = (const float*)d_in[9];
    const float* beta  = (const float*)d_in[10];
    const float* bnm   = (const float*)d_in[11];
    const float* bnv   = (const float*)d_in[12];
    float* out = (float*)d_out;

    int n = in_sizes[0] / 2;
    int E = in_sizes[1] / 2;
    const int* srcp = eidx;
    const int* dstp = eidx + E;

    cudaFuncSetAttribute(k_mma<128, 256, false, true, true>,
                         cudaFuncAttributeMaxDynamicSharedMemorySize, MMA_SMEM);
    cudaFuncSetAttribute(k_mma<256, 128, true, true, false>,
                         cudaFuncAttributeMaxDynamicSharedMemorySize, MMA_SMEM);
    cudaFuncSetAttribute(k_mma<256, 128, true, false, false>,
                         cudaFuncAttributeMaxDynamicSharedMemorySize, MMA_SMEM);

    void *ph, *pah, *pal, *pmh, *pml, *p1h, *p1l, *p2h, *p2l;
    cudaGetSymbolAddress(&ph, g_h);
    cudaGetSymbolAddress(&pah, g_aggh);
    cudaGetSymbolAddress(&pal, g_aggl);
    cudaGetSymbolAddress(&pmh, g_midh);
    cudaGetSymbolAddress(&pml, g_midl);
    cudaGetSymbolAddress(&p1h, g_w1h);
    cudaGetSymbolAddress(&p1l, g_w1l);
    cudaGetSymbolAddress(&p2h, g_w2h);
    cudaGetSymbolAddress(&p2l, g_w2l);
    float* H = (float*)ph;
    __nv_bfloat16* AGH = (__nv_bfloat16*)pah;
    __nv_bfloat16* AGL = (__nv_bfloat16*)pal;
    __nv_bfloat16* MIDH = (__nv_bfloat16*)pmh;
    __nv_bfloat16* MIDL = (__nv_bfloat16*)pml;
    const __nv_bfloat16* W1H = (const __nv_bfloat16*)p1h;
    const __nv_bfloat16* W1L = (const __nv_bfloat16*)p1l;
    const __nv_bfloat16* W2H = (const __nv_bfloat16*)p2h;
    const __nv_bfloat16* W2L = (const __nv_bfloat16*)p2l;

    int nblk = (n + 1023) / 1024;

    k_wt<<<(WSZ + 255) / 256, 256>>>(w1, w2);
    k_zero<<<(n * 18 + 255) / 256, 256>>>(n);
    k_count<<<(E + 255) / 256, 256>>>(dstp, eattr, E);
    k_bsum<<<nblk, 1024>>>(n);
    k_boff<<<1, 128>>>(nblk);
    k_local<<<nblk, 1024>>>(n);
    k_fill<<<(E + 255) / 256, 256>>>(srcp, dstp, E);
    k_embed<<<(n * 32 + 255) / 256, 256>>>(x, xemb, n);

    int mblocks = (n + 127) / 128;
    for (int l = 0; l < NLAYER; l++) {
        k_agg<<<(n * 32 + 255) / 256, 256>>>(etab + (size_t)l * 9 * DIM, n);
        // GEMM1: agg(bf16 hi/lo) @ W1^T -> MID bf16 hi/lo, bias+ReLU
        k_mma<128, 256, false, true, true><<<dim3(mblocks, 2), 256, MMA_SMEM>>>(
            AGH, AGL,
            W1H + (size_t)l * 256 * 128, W1L + (size_t)l * 256 * 128,
            b1 + (size_t)l * 2 * DIM,
            nullptr, nullptr, nullptr, nullptr, nullptr, MIDH, MIDL, n);
        // GEMM2: MID(bf16 hi/lo) @ W2^T -> H/out fp32, bias+BN(+ReLU)
        const float* g = gamma + (size_t)l * DIM;
        const float* bt = beta + (size_t)l * DIM;
        const float* mn = bnm + (size_t)l * DIM;
        const float* vr = bnv + (size_t)l * DIM;
        const __nv_bfloat16* W2Hl = W2H + (size_t)l * 128 * 256;
        const __nv_bfloat16* W2Ll = W2L + (size_t)l * 128 * 256;
        const float* B2 = b2 + (size_t)l * DIM;
        if (l < NLAYER - 1) {
            k_mma<256, 128, true, true, false><<<dim3(mblocks, 1), 256, MMA_SMEM>>>(
                MIDH, MIDL, W2Hl, W2Ll, B2, g, bt, mn, vr, H, nullptr, nullptr, n);
        } else {
            k_mma<256, 128, true, false, false><<<dim3(mblocks, 1), 256, MMA_SMEM>>>(
                MIDH, MIDL, W2Hl, W2Ll, B2, g, bt, mn, vr, out, nullptr, nullptr, n);
        }
    }
}

// round 16
// speedup vs baseline: 1.4506x; 1.2378x over previous
#include <cuda_runtime.h>
#include <cuda_fp16.h>
#include <cstdint>

#define N_NODES 100000
#define N_EDGES 1600000
#define DIM 128
#define NLAYER 5

// ---------------- scratch (device globals; no allocations) ----------------
__device__ float g_h[N_NODES * DIM];                 // node features fp32
__device__ __half g_agg16[N_NODES * DIM];            // aggregated fp16
__device__ __half g_mid16[N_NODES * 2 * DIM];        // MLP hidden fp16
__device__ int   g_rowptr[N_NODES + 1];
__device__ int   g_cursor[N_NODES];
__device__ int   g_cnt[N_NODES];
__device__ int   g_tcnt[N_NODES * 18];               // per-node edge-type histogram
__device__ int   g_edge[N_EDGES];                    // src only
__device__ int   g_bsum[128];
__device__ int   g_boff[128];

#define WSZ (NLAYER * 256 * 128)
__device__ __half g_w1h[WSZ];
__device__ __half g_w1l[WSZ];
__device__ __half g_w2h[WSZ];
__device__ __half g_w2l[WSZ];

// ---------------- setup: weight fp16 hi/lo split + zero counters (fused) ----------------
__global__ void k_wt(const float* __restrict__ w1, const float* __restrict__ w2, int n) {
    int i = blockIdx.x * blockDim.x + threadIdx.x;
    if (i < n) g_cnt[i] = 0;
    if (i < n * 18) g_tcnt[i] = 0;
    if (i < WSZ) {
        float a = w1[i];
        __half h = __float2half_rn(a);
        g_w1h[i] = h;
        g_w1l[i] = __float2half_rn(a - __half2float(h));
        float b = w2[i];
        __half h2 = __float2half_rn(b);
        g_w2h[i] = h2;
        g_w2l[i] = __float2half_rn(b - __half2float(h2));
    }
}

__global__ void k_count(const int* __restrict__ dst, const int* __restrict__ eattr, int E) {
    int e = blockIdx.x * blockDim.x + threadIdx.x;
    if (e >= E) return;
    int d = dst[e];
    atomicAdd(&g_cnt[d], 1);
    int ci = eattr[2 * e] * 3 + eattr[2 * e + 1];
    atomicAdd(&g_tcnt[d * 18 + ci], 1);
}

__global__ void k_bsum(int n) {
    __shared__ int wsum[32];
    int i = blockIdx.x * 1024 + threadIdx.x;
    int lane = threadIdx.x & 31, wid = threadIdx.x >> 5;
    int v = (i < n) ? g_cnt[i] : 0;
    int s = v;
    #pragma unroll
    for (int o = 16; o > 0; o >>= 1) s += __shfl_down_sync(0xffffffffu, s, o);
    if (lane == 0) wsum[wid] = s;
    __syncthreads();
    if (wid == 0) {
        int t = wsum[lane];
        #pragma unroll
        for (int o = 16; o > 0; o >>= 1) t += __shfl_down_sync(0xffffffffu, t, o);
        if (lane == 0) g_bsum[blockIdx.x] = t;
    }
}
__global__ void k_boff(int nblk) {
    __shared__ int ws[4];
    int lane = threadIdx.x & 31, wid = threadIdx.x >> 5;
    int v = (threadIdx.x < nblk) ? g_bsum[threadIdx.x] : 0;
    int s = v;
    #pragma unroll
    for (int o = 1; o < 32; o <<= 1) {
        int t = __shfl_up_sync(0xffffffffu, s, o);
        if (lane >= o) s += t;
    }
    if (lane == 31) ws[wid] = s;
    __syncthreads();
    if (wid == 0 && lane < 4) {
        int t = ws[lane];
        #pragma unroll
        for (int o = 1; o < 4; o <<= 1) {
            int u = __shfl_up_sync(0xfu, t, o);
            if (lane >= o) t += u;
        }
        ws[lane] = t;
    }
    __syncthreads();
    int excl = s - v + (wid ? ws[wid - 1] : 0);
    if (threadIdx.x < nblk) g_boff[threadIdx.x] = excl;
}
__global__ void k_local(int n) {
    __shared__ int wsum[32];
    int i = blockIdx.x * 1024 + threadIdx.x;
    int lane = threadIdx.x & 31, wid = threadIdx.x >> 5;
    int v = (i < n) ? g_cnt[i] : 0;
    int s = v;
    #pragma unroll
    for (int o = 1; o < 32; o <<= 1) {
        int t = __shfl_up_sync(0xffffffffu, s, o);
        if (lane >= o) s += t;
    }
    if (lane == 31) wsum[wid] = s;
    __syncthreads();
    if (wid == 0) {
        int t = wsum[lane];
        #pragma unroll
        for (int o = 1; o < 32; o <<= 1) {
            int u = __shfl_up_sync(0xffffffffu, t, o);
            if (lane >= o) t += u;
        }
        wsum[lane] = t;
    }
    __syncthreads();
    int excl = s - v + (wid ? wsum[wid - 1] : 0) + g_boff[blockIdx.x];
    if (i < n) {
        g_rowptr[i] = excl;
        g_cursor[i] = excl;
        if (i == n - 1) g_rowptr[n] = excl + v;
    }
}
__global__ void k_fill(const int* __restrict__ src, const int* __restrict__ dst, int E) {
    int e = blockIdx.x * blockDim.x + threadIdx.x;
    if (e >= E) return;
    int d = dst[e];
    int pos = atomicAdd(&g_cursor[d], 1);
    g_edge[pos] = src[e];
}

// ---------------- node input embedding ----------------
__global__ void k_embed(const int* __restrict__ x, const float* __restrict__ xemb, int n) {
    int i = blockIdx.x * blockDim.x + threadIdx.x;
    int v = i >> 5, c = (i & 31) * 4;
    if (v >= n) return;
    int a = x[2 * v], ch = x[2 * v + 1];
    float4 va = *(const float4*)(xemb + (size_t)a * DIM + c);
    float4 vb = *(const float4*)(xemb + (size_t)(120 + ch) * DIM + c);
    float4 r;
    r.x = va.x + vb.x; r.y = va.y + vb.y; r.z = va.z + vb.z; r.w = va.w + vb.w;
    *(float4*)(g_h + (size_t)v * DIM + c) = r;
}

// ---------------- aggregation: one warp per node, outputs fp16 ----------------
__global__ void k_agg(const float* __restrict__ etab_l, int n) {
    __shared__ float4 ctb[18 * 32];
    for (int i = threadIdx.x; i < 18 * 32; i += blockDim.x) {
        int comb = i >> 5, ln = i & 31;
        int eb = comb / 3, ed = comb - eb * 3;
        float4 b = ((const float4*)etab_l)[eb * 32 + ln];
        float4 d = ((const float4*)(etab_l + 6 * DIM))[ed * 32 + ln];
        ctb[i] = make_float4(b.x + d.x, b.y + d.y, b.z + d.z, b.w + d.w);
    }
    __syncthreads();
    int w = (blockIdx.x * blockDim.x + threadIdx.x) >> 5;
    int lane = threadIdx.x & 31;
    if (w >= n) return;
    int beg = g_rowptr[w], end = g_rowptr[w + 1];
    float4 acc0 = *(const float4*)(g_h + (size_t)w * DIM + lane * 4);
    float4 acc1 = make_float4(0.f, 0.f, 0.f, 0.f);
    float4 acc2 = make_float4(0.f, 0.f, 0.f, 0.f);
    float4 acc3 = make_float4(0.f, 0.f, 0.f, 0.f);
    const int* tc = g_tcnt + (size_t)w * 18;
    #pragma unroll
    for (int t = 0; t < 18; t++) {
        float c = (float)(tc[t] + (t == 12 ? 1 : 0));
        float4 e = ctb[t * 32 + lane];
        acc0.x += c * e.x; acc0.y += c * e.y;
        acc0.z += c * e.z; acc0.w += c * e.w;
    }
    int p = beg;
    for (; p + 4 <= end; p += 4) {
        int s0 = g_edge[p], s1 = g_edge[p + 1], s2 = g_edge[p + 2], s3 = g_edge[p + 3];
        float4 h0 = *(const float4*)(g_h + (size_t)s0 * DIM + lane * 4);
        float4 h1 = *(const float4*)(g_h + (size_t)s1 * DIM + lane * 4);
        float4 h2 = *(const float4*)(g_h + (size_t)s2 * DIM + lane * 4);
        float4 h3 = *(const float4*)(g_h + (size_t)s3 * DIM + lane * 4);
        acc0.x += h0.x; acc0.y += h0.y; acc0.z += h0.z; acc0.w += h0.w;
        acc1.x += h1.x; acc1.y += h1.y; acc1.z += h1.z; acc1.w += h1.w;
        acc2.x += h2.x; acc2.y += h2.y; acc2.z += h2.z; acc2.w += h2.w;
        acc3.x += h3.x; acc3.y += h3.y; acc3.z += h3.z; acc3.w += h3.w;
    }
    for (; p < end; p++) {
        int s = g_edge[p];
        float4 hv = *(const float4*)(g_h + (size_t)s * DIM + lane * 4);
        acc0.x += hv.x; acc0.y += hv.y; acc0.z += hv.z; acc0.w += hv.w;
    }
    acc0.x += acc1.x + acc2.x + acc3.x;
    acc0.y += acc1.y + acc2.y + acc3.y;
    acc0.z += acc1.z + acc2.z + acc3.z;
    acc0.w += acc1.w + acc2.w + acc3.w;
    __half2 p0 = __floats2half2_rn(acc0.x, acc0.y);
    __half2 p1 = __floats2half2_rn(acc0.z, acc0.w);
    size_t o = (size_t)w * DIM + lane * 4;
    *(uint2*)(g_agg16 + o) = make_uint2(*(uint32_t*)&p0, *(uint32_t*)&p1);
}

// ---------------- pipelined fp16 mma GEMM, 2 CTAs/SM ----------------
// C[M,JTOT] = A[M,KTOT] @ W[JTOT,KTOT]^T. A fp16 single; W pre-split fp16 hi/lo.
// D = A*Wh + A*Wl (fp32 accum). CTA 128x128, 8 warps, 32-wide K chunks,
// 2-stage cp.async double buffer. Stage = A | BH | BL tiles.
#define SROWB 80                            // 64B data + 16B pad per 32-k row
#define TILE_B (128 * SROWB)                // 10240
#define STAGE_B (3 * TILE_B)                // 30720: A | BHI | BLO
#define MMA_SMEM (1024 + 2 * STAGE_B)       // 62464

__device__ __forceinline__ uint32_t smem_u32(const void* p) {
    uint32_t a;
    asm("{ .reg .u64 t; cvta.to.shared.u64 t, %1; cvt.u32.u64 %0, t; }" : "=r"(a) : "l"(p));
    return a;
}
__device__ __forceinline__ void cpa16(uint32_t dst, const void* src, int sz) {
    asm volatile("cp.async.cg.shared.global [%0], [%1], 16, %2;"
                 :: "r"(dst), "l"(src), "r"(sz) : "memory");
}
#define CP_COMMIT() asm volatile("cp.async.commit_group;" ::: "memory")
template <int N> __device__ __forceinline__ void cp_wait() {
    asm volatile("cp.async.wait_group %0;" :: "n"(N) : "memory");
}
__device__ __forceinline__ void ldsm4(uint32_t* r, uint32_t addr) {
    asm volatile("ldmatrix.sync.aligned.m8n8.x4.shared.b16 {%0,%1,%2,%3}, [%4];"
                 : "=r"(r[0]), "=r"(r[1]), "=r"(r[2]), "=r"(r[3]) : "r"(addr));
}
__device__ __forceinline__ void mma16816(float* d, const uint32_t* a,
                                         uint32_t b0, uint32_t b1) {
    asm volatile(
        "mma.sync.aligned.m16n8k16.row.col.f32.f16.f16.f32 "
        "{%0,%1,%2,%3}, {%4,%5,%6,%7}, {%8,%9}, {%0,%1,%2,%3};"
        : "+f"(d[0]), "+f"(d[1]), "+f"(d[2]), "+f"(d[3])
        : "r"(a[0]), "r"(a[1]), "r"(a[2]), "r"(a[3]), "r"(b0), "r"(b1));
}

template <int KTOT, int JTOT, bool BN, bool RELU, bool OHALF>
__global__ void __launch_bounds__(256, 2)
k_mma(const __half* __restrict__ A,
      const __half* __restrict__ Wh, const __half* __restrict__ Wl,
      const float* __restrict__ bias,
      const float* __restrict__ gamma, const float* __restrict__ beta,
      const float* __restrict__ mean, const float* __restrict__ var,
      float* __restrict__ C, __half* __restrict__ Oh, int M) {
    extern __shared__ char sm[];
    uint32_t sb = smem_u32(sm);
    float* s_scale = (float*)(sm);
    float* s_shift = (float*)(sm + 512);
    int tid = threadIdx.x;
    int wid = tid >> 5, lane = tid & 31;
    int mb = blockIdx.x, jbase = blockIdx.y * 128;
    int wm = wid >> 1, wn = wid & 1;

    if (tid < 128) {
        int j = jbase + tid;
        if (BN) {
            float s = gamma[j] * rsqrtf(var[j] + 1e-5f);
            s_scale[tid] = s;
            s_shift[tid] = (bias[j] - mean[j]) * s + beta[j];
        } else {
            s_scale[tid] = 1.f;
            s_shift[tid] = bias[j];
        }
    }

    float acc[2][8][4];
    #pragma unroll
    for (int a = 0; a < 2; a++)
        #pragma unroll
        for (int b = 0; b < 8; b++)
            #pragma unroll
            for (int c = 0; c < 4; c++) acc[a][b][c] = 0.f;

    int lr = lane & 15, lc8 = lane >> 4;
    constexpr int NKB = KTOT / 32;

    // staging: pure 16B cp.async copies (A single tile + B hi/lo), 32-wide K chunk
    auto stage_load = [&](int s, int kb) {
        uint32_t stb = sb + 1024 + s * STAGE_B;
        #pragma unroll
        for (int t = 0; t < 2; t++) {
            int idx = tid + t * 256;          // 0..511
            int row = idx >> 2;               // 0..127
            int k8 = (idx & 3) * 8;           // 0,8,16,24
            int rg = mb * 128 + row;
            int sz = (rg < M) ? 16 : 0;
            cpa16(stb + row * SROWB + k8 * 2, A + (size_t)rg * KTOT + kb + k8, sz);
        }
        #pragma unroll
        for (int t = 0; t < 2; t++) {
            int idx = tid + t * 256;
            int j = idx >> 2;
            int k8 = (idx & 3) * 8;
            size_t gsrc = (size_t)(jbase + j) * KTOT + kb + k8;
            uint32_t off = stb + TILE_B + j * SROWB + k8 * 2;
            cpa16(off, Wh + gsrc, 16);
            cpa16(off + TILE_B, Wl + gsrc, 16);
        }
    };

    stage_load(0, 0);
    CP_COMMIT();

    #pragma unroll
    for (int i = 0; i < NKB; i++) {
        if (i + 1 < NKB) {
            stage_load((i + 1) & 1, (i + 1) * 32);
            CP_COMMIT();
            cp_wait<1>();
        } else {
            cp_wait<0>();
        }
        __syncthreads();

        uint32_t stb = sb + 1024 + (i & 1) * STAGE_B;
        #pragma unroll
        for (int ks = 0; ks < 2; ks++) {
            uint32_t a[2][4];
            #pragma unroll
            for (int mf = 0; mf < 2; mf++) {
                uint32_t aoff = stb + (uint32_t)((wm * 32 + mf * 16 + lr) * SROWB +
                                                 ks * 32 + lc8 * 16);
                ldsm4(a[mf], aoff);
            }
            #pragma unroll
            for (int p = 0; p < 4; p++) {
                uint32_t bh[4], bl[4];
                uint32_t boff = stb + TILE_B +
                                (uint32_t)((wn * 64 + p * 16 + lr) * SROWB +
                                           ks * 32 + lc8 * 16);
                ldsm4(bh, boff);
                ldsm4(bl, boff + TILE_B);
                #pragma unroll
                for (int mf = 0; mf < 2; mf++) {
                    mma16816(acc[mf][2 * p],     a[mf], bh[0], bh[2]);
                    mma16816(acc[mf][2 * p],     a[mf], bl[0], bl[2]);
                    mma16816(acc[mf][2 * p + 1], a[mf], bh[1], bh[3]);
                    mma16816(acc[mf][2 * p + 1], a[mf], bl[1], bl[3]);
                }
            }
        }
        __syncthreads();
    }

    // epilogue
    #pragma unroll
    for (int mf = 0; mf < 2; mf++) {
        int row0 = mb * 128 + wm * 32 + mf * 16 + (lane >> 2);
        int row1 = row0 + 8;
        #pragma unroll
        for (int nf = 0; nf < 8; nf++) {
            int col = wn * 64 + nf * 8 + (lane & 3) * 2;
            float s0 = s_scale[col], s1 = s_scale[col + 1];
            float t0 = s_shift[col], t1 = s_shift[col + 1];
            float v0 = acc[mf][nf][0] * s0 + t0;
            float v1 = acc[mf][nf][1] * s1 + t1;
            float v2 = acc[mf][nf][2] * s0 + t0;
            float v3 = acc[mf][nf][3] * s1 + t1;
            if (RELU) {
                v0 = fmaxf(v0, 0.f); v1 = fmaxf(v1, 0.f);
                v2 = fmaxf(v2, 0.f); v3 = fmaxf(v3, 0.f);
            }
            if (OHALF) {
                if (row0 < M) {
                    __half2 hp = __floats2half2_rn(v0, v1);
                    *(uint32_t*)(Oh + (size_t)row0 * JTOT + jbase + col) = *(uint32_t*)&hp;
                }
                if (row1 < M) {
                    __half2 hp = __floats2half2_rn(v2, v3);
                    *(uint32_t*)(Oh + (size_t)row1 * JTOT + jbase + col) = *(uint32_t*)&hp;
                }
            } else {
                if (row0 < M)
                    *(float2*)(C + (size_t)row0 * JTOT + jbase + col) = make_float2(v0, v1);
                if (row1 < M)
                    *(float2*)(C + (size_t)row1 * JTOT + jbase + col) = make_float2(v2, v3);
            }
        }
    }
}

// ---------------- launch ----------------
extern "C" void kernel_launch(void* const* d_in, const int* in_sizes, int n_in,
                              void* d_out, int out_size) {
    const int*   x     = (const int*)d_in[0];
    const int*   eidx  = (const int*)d_in[1];
    const int*   eattr = (const int*)d_in[2];
    const float* xemb  = (const float*)d_in[3];
    const float* etab  = (const float*)d_in[4];
    const float* w1    = (const float*)d_in[5];
    const float* b1    = (const float*)d_in[6];
    const float* w2    = (const float*)d_in[7];
    const float* b2    = (const float*)d_in[8];
    const float* gamma = (const float*)d_in[9];
    const float* beta  = (const float*)d_in[10];
    const float* bnm   = (const float*)d_in[11];
    const float* bnv   = (const float*)d_in[12];
    float* out = (float*)d_out;

    int n = in_sizes[0] / 2;
    int E = in_sizes[1] / 2;
    const int* srcp = eidx;
    const int* dstp = eidx + E;

    cudaFuncSetAttribute(k_mma<128, 256, false, true, true>,
                         cudaFuncAttributeMaxDynamicSharedMemorySize, MMA_SMEM);
    cudaFuncSetAttribute(k_mma<256, 128, true, true, false>,
                         cudaFuncAttributeMaxDynamicSharedMemorySize, MMA_SMEM);
    cudaFuncSetAttribute(k_mma<256, 128, true, false, false>,
                         cudaFuncAttributeMaxDynamicSharedMemorySize, MMA_SMEM);

    void *ph, *pag, *pmid, *p1h, *p1l, *p2h, *p2l;
    cudaGetSymbolAddress(&ph, g_h);
    cudaGetSymbolAddress(&pag, g_agg16);
    cudaGetSymbolAddress(&pmid, g_mid16);
    cudaGetSymbolAddress(&p1h, g_w1h);
    cudaGetSymbolAddress(&p1l, g_w1l);
    cudaGetSymbolAddress(&p2h, g_w2h);
    cudaGetSymbolAddress(&p2l, g_w2l);
    float* H = (float*)ph;
    __half* AG16 = (__half*)pag;
    __half* MID16 = (__half*)pmid;
    const __half* W1H = (const __half*)p1h;
    const __half* W1L = (const __half*)p1l;
    const __half* W2H = (const __half*)p2h;
    const __half* W2L = (const __half*)p2l;

    int nblk = (n + 1023) / 1024;

    k_wt<<<(n * 18 + 255) / 256, 256>>>(w1, w2, n);
    k_count<<<(E + 255) / 256, 256>>>(dstp, eattr, E);
    k_bsum<<<nblk, 1024>>>(n);
    k_boff<<<1, 128>>>(nblk);
    k_local<<<nblk, 1024>>>(n);
    k_fill<<<(E + 255) / 256, 256>>>(srcp, dstp, E);
    k_embed<<<(n * 32 + 255) / 256, 256>>>(x, xemb, n);

    int mblocks = (n + 127) / 128;
    for (int l = 0; l < NLAYER; l++) {
        k_agg<<<(n * 32 + 255) / 256, 256>>>(etab + (size_t)l * 9 * DIM, n);
        // GEMM1: agg(fp16) @ W1^T -> MID fp16, bias+ReLU
        k_mma<128, 256, false, true, true><<<dim3(mblocks, 2), 256, MMA_SMEM>>>(
            AG16,
            W1H + (size_t)l * 256 * 128, W1L + (size_t)l * 256 * 128,
            b1 + (size_t)l * 2 * DIM,
            nullptr, nullptr, nullptr, nullptr, nullptr, MID16, n);
        // GEMM2: MID(fp16) @ W2^T -> H/out fp32, bias+BN(+ReLU)
        const float* g = gamma + (size_t)l * DIM;
        const float* bt = beta + (size_t)l * DIM;
        const float* mn = bnm + (size_t)l * DIM;
        const float* vr = bnv + (size_t)l * DIM;
        const __half* W2Hl = W2H + (size_t)l * 128 * 256;
        const __half* W2Ll = W2L + (size_t)l * 128 * 256;
        const float* B2 = b2 + (size_t)l * DIM;
        if (l < NLAYER - 1) {
            k_mma<256, 128, true, true, false><<<dim3(mblocks, 1), 256, MMA_SMEM>>>(
                MID16, W2Hl, W2Ll, B2, g, bt, mn, vr, H, nullptr, n);
        } else {
            k_mma<256, 128, true, false, false><<<dim3(mblocks, 1), 256, MMA_SMEM>>>(
                MID16, W2Hl, W2Ll, B2, g, bt, mn, vr, out, nullptr, n);
        }
    }
}